// round 5
// baseline (speedup 1.0000x reference)
#include <cuda_runtime.h>
#include <cuda_bf16.h>
#include <cstdint>

// Problem constants
#define BB 2
#define TT 2048
#define DD 1024
#define HH 16
#define DHH 64
#define MM (BB*TT)          // 4096 rows

// ---------------------------------------------------------------------------
// Scratch (device globals: no runtime allocation allowed)
// ---------------------------------------------------------------------------
__device__ float g_qc[MM*DD];          // x@Wq (pre-conv), [M,D]
__device__ float g_kc[MM*DD];
__device__ float g_vc[MM*DD];
__device__ float g_q [MM*DD];          // post conv/silu/l2norm, [B,H,T,DH]
__device__ float g_k [MM*DD];
__device__ float g_v [MM*DD];
__device__ float g_beta[BB*HH*TT];     // [B,H,T]
__device__ float g_o [MM*DD];          // scan output, [B,H,T,DH]

// bf16 split operands for tensor-core GEMMs
__device__ __nv_bfloat16 g_xh[MM*DD];  // x hi, [M,K]
__device__ __nv_bfloat16 g_xl[MM*DD];  // x lo
__device__ __nv_bfloat16 g_oh[MM*DD];  // rmsnormed output hi, [M,K]
__device__ __nv_bfloat16 g_ol[MM*DD];
__device__ __nv_bfloat16 g_wh[4][DD*DD]; // W^T hi [N,K] for Wq,Wk,Wv,Wo
__device__ __nv_bfloat16 g_wl[4][DD*DD];

// ---------------------------------------------------------------------------
// f32x2 packed helpers (Blackwell FFMA2)
// ---------------------------------------------------------------------------
__device__ __forceinline__ unsigned long long dup2(float x){
  unsigned long long r;
  unsigned u = __float_as_uint(x);
  asm("mov.b64 %0, {%1, %1};" : "=l"(r) : "r"(u));
  return r;
}
__device__ __forceinline__ void ffma2(unsigned long long &c, unsigned long long a, unsigned long long b){
  asm("fma.rn.f32x2 %0, %1, %2, %0;" : "+l"(c) : "l"(a), "l"(b));
}
__device__ __forceinline__ float2 unpk2(unsigned long long p){
  unsigned lo, hi;
  asm("mov.b64 {%0, %1}, %2;" : "=r"(lo), "=r"(hi) : "l"(p));
  return make_float2(__uint_as_float(lo), __uint_as_float(hi));
}

// ---------------------------------------------------------------------------
// smem / cp.async / mma helpers (all base compute_103-legal: sm_80 era)
// ---------------------------------------------------------------------------
__device__ __forceinline__ uint32_t smem_u32(const void* p){
  uint32_t a;
  asm("{ .reg .u64 t; cvta.to.shared.u64 t, %1; cvt.u32.u64 %0, t; }" : "=r"(a) : "l"(p));
  return a;
}
__device__ __forceinline__ void cpasync16(uint32_t dst, const void* src){
  asm volatile("cp.async.cg.shared.global [%0], [%1], 16;" :: "r"(dst), "l"(src));
}
__device__ __forceinline__ void cpasync_commit(){
  asm volatile("cp.async.commit_group;" ::: "memory");
}
__device__ __forceinline__ void ldm4(uint32_t* r, uint32_t addr){
  asm volatile("ldmatrix.sync.aligned.m8n8.x4.shared.b16 {%0,%1,%2,%3}, [%4];"
               : "=r"(r[0]), "=r"(r[1]), "=r"(r[2]), "=r"(r[3]) : "r"(addr));
}
__device__ __forceinline__ void mma16816(float* d, const uint32_t* a, const uint32_t* b){
  asm volatile(
    "mma.sync.aligned.m16n8k16.row.col.f32.bf16.bf16.f32 "
    "{%0,%1,%2,%3}, {%4,%5,%6,%7}, {%8,%9}, {%0,%1,%2,%3};"
    : "+f"(d[0]), "+f"(d[1]), "+f"(d[2]), "+f"(d[3])
    : "r"(a[0]), "r"(a[1]), "r"(a[2]), "r"(a[3]), "r"(b[0]), "r"(b[1]));
}

// ---------------------------------------------------------------------------
// Tensor-pipe GEMM: C[M,1024] = (Ah+Al)[M,1024] @ (Bh+Bl)^T, B stored [N,K].
// 3-term bf16 split, fp32 accum. Tile 128x128, K-chunk 32, 2-stage cp.async.
// 8 warps = 2(M) x 4(N); warp tile 64x32 = 4 m-tiles x 4 n-tiles of m16n8.
// smem rows padded to 80B -> conflict-free ldmatrix.
// ---------------------------------------------------------------------------
#define GK   1024
#define KC   32
#define NCH  (GK/KC)           // 32 chunks
#define ROWB 80                // bytes per smem row (32 bf16 + 8 pad)
#define MATB (128*ROWB)        // 10240 B per matrix tile
#define STAGEB (4*MATB)        // Ah,Al,Bh,Bl = 40960
#define GEMM_SMEM (2*STAGEB)   // 81920

__global__ __launch_bounds__(256, 2)
void gemm_mma(const __nv_bfloat16* __restrict__ Ah, const __nv_bfloat16* __restrict__ Al,
              const __nv_bfloat16* __restrict__ Bh, const __nv_bfloat16* __restrict__ Bl,
              float* __restrict__ C)
{
  extern __shared__ char smem[];
  const uint32_t sb = smem_u32(smem);
  const int tid   = threadIdx.x;
  const int wid   = tid >> 5;
  const int lane  = tid & 31;
  const int warpM = wid & 1;       // 0..1
  const int warpN = wid >> 1;      // 0..3
  const int tileM = blockIdx.y * 128;
  const int tileN = blockIdx.x * 128;

  const __nv_bfloat16* gsrc[4] = {
    Ah + (size_t)tileM * GK, Al + (size_t)tileM * GK,
    Bh + (size_t)tileN * GK, Bl + (size_t)tileN * GK };

  // loader: 4 matrices x 128 rows x 4 chunks(16B) = 2048 chunks, 8 per thread
  auto load_stage = [&](int s, int kt){
    const uint32_t base = sb + s * STAGEB;
    #pragma unroll
    for (int i = 0; i < 8; i++){
      int cid = tid + i * 256;
      int mat = cid >> 9;
      int rem = cid & 511;
      int row = rem >> 2, ch = rem & 3;
      cpasync16(base + mat * MATB + row * ROWB + ch * 16,
                gsrc[mat] + (size_t)row * GK + kt + ch * 8);
    }
  };

  float acc[4][4][4];
  #pragma unroll
  for (int mt = 0; mt < 4; mt++)
    #pragma unroll
    for (int nt = 0; nt < 4; nt++)
      #pragma unroll
      for (int j = 0; j < 4; j++) acc[mt][nt][j] = 0.f;

  // per-lane ldmatrix address components
  const int aRow   = lane & 15;
  const int aKhalf = lane >> 4;                       // 0/1
  const uint32_t aOff = (uint32_t)(warpM*64 + aRow) * ROWB + aKhalf * 16;
  const int bRow   = (lane & 7) + ((lane >> 4) << 3); // 0..15
  const int bKhalf = (lane >> 3) & 1;
  const uint32_t bOff = (uint32_t)(warpN*32 + bRow) * ROWB + bKhalf * 16;

  load_stage(0, 0);  cpasync_commit();
  load_stage(1, KC); cpasync_commit();

  for (int c = 0; c < NCH; c++){
    if (c < NCH - 1) asm volatile("cp.async.wait_group 1;" ::: "memory");
    else             asm volatile("cp.async.wait_group 0;" ::: "memory");
    __syncthreads();

    const uint32_t sbuf = sb + (c & 1) * STAGEB;
    #pragma unroll
    for (int ks = 0; ks < 2; ks++){
      const uint32_t koff = ks * 32;
      uint32_t ah[4][4], bh[2][4], bl[2][4];
      #pragma unroll
      for (int mt = 0; mt < 4; mt++)
        ldm4(ah[mt], sbuf + 0*MATB + aOff + mt*16*ROWB + koff);
      #pragma unroll
      for (int p = 0; p < 2; p++)
        ldm4(bh[p], sbuf + 2*MATB + bOff + p*16*ROWB + koff);
      #pragma unroll
      for (int mt = 0; mt < 4; mt++)
        #pragma unroll
        for (int nt = 0; nt < 4; nt++)
          mma16816(acc[mt][nt], ah[mt], &bh[nt>>1][(nt&1)*2]);
      #pragma unroll
      for (int p = 0; p < 2; p++)
        ldm4(bl[p], sbuf + 3*MATB + bOff + p*16*ROWB + koff);
      #pragma unroll
      for (int mt = 0; mt < 4; mt++)
        #pragma unroll
        for (int nt = 0; nt < 4; nt++)
          mma16816(acc[mt][nt], ah[mt], &bl[nt>>1][(nt&1)*2]);
      #pragma unroll
      for (int mt = 0; mt < 4; mt++){
        uint32_t al_[4];
        ldm4(al_, sbuf + 1*MATB + aOff + mt*16*ROWB + koff);
        #pragma unroll
        for (int nt = 0; nt < 4; nt++)
          mma16816(acc[mt][nt], al_, &bh[nt>>1][(nt&1)*2]);
      }
    }
    __syncthreads();
    if (c + 2 < NCH){ load_stage(c & 1, (c + 2) * KC); cpasync_commit(); }
  }

  // epilogue
  const int rBase = tileM + warpM*64 + (lane >> 2);
  const int cBase = tileN + warpN*32 + (lane & 3) * 2;
  #pragma unroll
  for (int mt = 0; mt < 4; mt++){
    #pragma unroll
    for (int nt = 0; nt < 4; nt++){
      float* p0 = C + (size_t)(rBase + mt*16)     * GK + cBase + nt*8;
      float* p1 = C + (size_t)(rBase + mt*16 + 8) * GK + cBase + nt*8;
      *(float2*)p0 = make_float2(acc[mt][nt][0], acc[mt][nt][1]);
      *(float2*)p1 = make_float2(acc[mt][nt][2], acc[mt][nt][3]);
    }
  }
}

// ---------------------------------------------------------------------------
// fp32 -> (hi, lo) bf16 split, same layout
// ---------------------------------------------------------------------------
__global__ void split_kernel(const float* __restrict__ X,
                             __nv_bfloat16* __restrict__ H, __nv_bfloat16* __restrict__ L)
{
  int i = (blockIdx.x * 256 + threadIdx.x) * 4;
  float4 xv = *(const float4*)(X + i);
  float xs[4] = {xv.x, xv.y, xv.z, xv.w};
  __nv_bfloat16 h[4], l[4];
  #pragma unroll
  for (int j = 0; j < 4; j++){
    h[j] = __float2bfloat16_rn(xs[j]);
    l[j] = __float2bfloat16_rn(xs[j] - __bfloat162float(h[j]));
  }
  *(__nv_bfloat162*)(H + i)     = __nv_bfloat162(h[0], h[1]);
  *(__nv_bfloat162*)(H + i + 2) = __nv_bfloat162(h[2], h[3]);
  *(__nv_bfloat162*)(L + i)     = __nv_bfloat162(l[0], l[1]);
  *(__nv_bfloat162*)(L + i + 2) = __nv_bfloat162(l[2], l[3]);
}

// ---------------------------------------------------------------------------
// Weight transpose + bf16 split: W[K,N] fp32 -> Wt hi/lo [N,K] bf16
// ---------------------------------------------------------------------------
__global__ void wsplit_kernel(const float* __restrict__ W,
                              __nv_bfloat16* __restrict__ TH, __nv_bfloat16* __restrict__ TL)
{
  __shared__ float tile[32][33];
  const int n0 = blockIdx.x * 32, k0 = blockIdx.y * 32;
  const int tx = threadIdx.x, ty = threadIdx.y;
  #pragma unroll
  for (int i = 0; i < 4; i++)
    tile[ty + i*8][tx] = W[(size_t)(k0 + ty + i*8) * DD + n0 + tx];
  __syncthreads();
  #pragma unroll
  for (int i = 0; i < 4; i++){
    float v = tile[tx][ty + i*8];
    __nv_bfloat16 h = __float2bfloat16_rn(v);
    __nv_bfloat16 l = __float2bfloat16_rn(v - __bfloat162float(h));
    size_t idx = (size_t)(n0 + ty + i*8) * DD + k0 + tx;
    TH[idx] = h; TL[idx] = l;
  }
}

// ---------------------------------------------------------------------------
// beta = sigmoid(x @ Wb)
// ---------------------------------------------------------------------------
__global__ void beta_kernel(const float* __restrict__ x, const float* __restrict__ Wb,
                            float* __restrict__ gb)
{
  const int m = blockIdx.x;
  const int tid = threadIdx.x;
  const int h = tid & 15, part = tid >> 4;
  __shared__ float sx[DD];
  for (int i = tid; i < DD/4; i += 64)
    *(float4*)&sx[i*4] = *(const float4*)&x[(size_t)m * DD + i*4];
  __syncthreads();
  float acc = 0.f;
  const int kbase = part * 256;
  for (int kk = 0; kk < 256; kk++)
    acc += sx[kbase + kk] * Wb[(size_t)(kbase + kk) * HH + h];
  __shared__ float red[64];
  red[tid] = acc;
  __syncthreads();
  if (tid < 16) {
    float s = red[tid] + red[tid+16] + red[tid+32] + red[tid+48];
    int b = m >> 11, t = m & (TT-1);
    gb[((size_t)b * HH + tid) * TT + t] = 1.f / (1.f + __expf(-s));
  }
}

// ---------------------------------------------------------------------------
// Causal depthwise conv (K=4) + SiLU (+ optional L2 norm), [M,D] -> [B,H,T,DH]
// ---------------------------------------------------------------------------
template<bool NORM>
__global__ void conv_kernel(const float* __restrict__ X, const float* __restrict__ W,
                            float* __restrict__ Y)
{
  const int m = blockIdx.x;
  const int b = m >> 11, t = m & (TT-1);
  const int tid = threadIdx.x;
  const int c0 = tid * 4;

  float warr[4][4];
  #pragma unroll
  for (int j = 0; j < 4; j++) {
    float4 wv = *(const float4*)&W[(size_t)(c0 + j) * 4];
    warr[j][0] = wv.x; warr[j][1] = wv.y; warr[j][2] = wv.z; warr[j][3] = wv.w;
  }
  float acc[4] = {0.f, 0.f, 0.f, 0.f};
  #pragma unroll
  for (int i = 0; i < 4; i++) {
    int tt = t - 3 + i;
    if (tt >= 0) {
      float4 xv = *(const float4*)&X[((size_t)(b * TT + tt)) * DD + c0];
      acc[0] += warr[0][i] * xv.x;
      acc[1] += warr[1][i] * xv.y;
      acc[2] += warr[2][i] * xv.z;
      acc[3] += warr[3][i] * xv.w;
    }
  }
  float y[4];
  #pragma unroll
  for (int j = 0; j < 4; j++) {
    float s = 1.f / (1.f + __expf(-acc[j]));
    y[j] = acc[j] * s;
  }
  float scale = 1.f;
  if (NORM) {
    float ss = y[0]*y[0] + y[1]*y[1] + y[2]*y[2] + y[3]*y[3];
    #pragma unroll
    for (int off = 8; off > 0; off >>= 1)
      ss += __shfl_xor_sync(0xffffffffu, ss, off, 16);
    scale = rsqrtf(ss + 1e-6f);
  }
  const int h = tid >> 4;
  const int dh0 = (tid & 15) * 4;
  *(float4*)&Y[(((size_t)(b * HH + h)) * TT + t) * DHH + dh0] =
      make_float4(y[0]*scale, y[1]*scale, y[2]*scale, y[3]*scale);
}

// ---------------------------------------------------------------------------
// Sequential delta-rule scan, v3. One block per (b,h). 128 threads = 4 warps.
// Warp w owns v-columns [w*16, w*16+16); lane = 2*colLocal + half; each thread
// holds a 32-row half of S[:,col] as 16 f32x2 regs. Cross-half reduction via
// one shfl_xor. k_t/q_t staged WARP-PRIVATELY (double-buffered) so the loop
// needs only __syncwarp — no block barrier; o-path overlaps next step.
// ---------------------------------------------------------------------------
__global__ __launch_bounds__(128, 1)
void scan_kernel(const float* __restrict__ gq, const float* __restrict__ gk,
                 const float* __restrict__ gv, const float* __restrict__ gb,
                 float* __restrict__ go)
{
  const int bh = blockIdx.x;
  const float* q  = gq + (size_t)bh * TT * DHH;
  const float* k  = gk + (size_t)bh * TT * DHH;
  const float* v  = gv + (size_t)bh * TT * DHH;
  const float* be = gb + (size_t)bh * TT;
  float* o        = go + (size_t)bh * TT * DHH;

  const int tid  = threadIdx.x;
  const int w    = tid >> 5;
  const int lane = tid & 31;
  const int colL = lane >> 1;        // 0..15
  const int half = lane & 1;         // 0/1 -> k rows [half*32, half*32+32)
  const int col  = w * 16 + colL;

  unsigned long long S2[16];
  #pragma unroll
  for (int i = 0; i < 16; i++) S2[i] = 0ull;

  // warp-private double-buffered staging: [warp][buf][0:64)=k_t, [64:128)=q_t
  __shared__ __align__(16) float skq[4][2][128];

  // stage t=0 (each lane loads 4 floats)
  {
    float4 s0 = (lane < 16) ? *(const float4*)&k[lane * 4]
                            : *(const float4*)&q[(lane - 16) * 4];
    *(float4*)&skq[w][0][lane * 4] = s0;
  }
  float vt = v[col];
  float bt = be[0];
  __syncwarp();

  for (int t = 0; t < TT; t++) {
    const int cur = t & 1, nxt = cur ^ 1;

    // prefetch t+1 (off critical path)
    float4 kqn = make_float4(0.f, 0.f, 0.f, 0.f);
    float vn = 0.f, bn = 0.f;
    if (t + 1 < TT) {
      kqn = (lane < 16) ? *(const float4*)&k[(size_t)(t + 1) * DHH + lane * 4]
                        : *(const float4*)&q[(size_t)(t + 1) * DHH + (lane - 16) * 4];
      vn = v[(size_t)(t + 1) * DHH + col];
      bn = be[t + 1];
    }

    const unsigned long long* kp = (const unsigned long long*)&skq[w][cur][half * 32];
    const unsigned long long* qp = (const unsigned long long*)&skq[w][cur][64 + half * 32];

    // kS partial over my 32 rows (2 split accumulators)
    unsigned long long a0 = 0ull, a1 = 0ull;
    #pragma unroll
    for (int i = 0; i < 8; i++) {
      ffma2(a0, kp[2*i],     S2[2*i]);
      ffma2(a1, kp[2*i + 1], S2[2*i + 1]);
    }
    float2 f0 = unpk2(a0), f1 = unpk2(a1);
    float part = (f0.x + f0.y) + (f1.x + f1.y);
    float kS = part + __shfl_xor_sync(0xffffffffu, part, 1);
    float u = bt * (vt - kS);
    unsigned long long u2 = dup2(u);

    // S += k u ; o_partial = q . S (o is off the recurrence critical path)
    unsigned long long o0 = 0ull, o1 = 0ull;
    #pragma unroll
    for (int i = 0; i < 8; i++) {
      ffma2(S2[2*i],     kp[2*i],     u2);  ffma2(o0, qp[2*i],     S2[2*i]);
      ffma2(S2[2*i + 1], kp[2*i + 1], u2);  ffma2(o1, qp[2*i + 1], S2[2*i + 1]);
    }
    float2 g0 = unpk2(o0), g1 = unpk2(o1);
    float op = (g0.x + g0.y) + (g1.x + g1.y);
    float oo = op + __shfl_xor_sync(0xffffffffu, op, 1);
    if (half == 0) o[(size_t)t * DHH + col] = oo;

    if (t + 1 < TT) {
      *(float4*)&skq[w][nxt][lane * 4] = kqn;
      vt = vn; bt = bn;
    }
    __syncwarp();
  }
}

// ---------------------------------------------------------------------------
// Per-head RMSNorm * rms_g, transpose [B,H,T,DH] -> [M,D], bf16 hi/lo split out
// ---------------------------------------------------------------------------
__global__ void rmsnorm_kernel(const float* __restrict__ O, const float* __restrict__ g,
                               __nv_bfloat16* __restrict__ YH, __nv_bfloat16* __restrict__ YL)
{
  const int m = blockIdx.x;
  const int b = m >> 11, t = m & (TT-1);
  const int tid = threadIdx.x;
  const int h = tid >> 4;
  const int dh0 = (tid & 15) * 4;

  float4 ov = *(const float4*)&O[(((size_t)(b * HH + h)) * TT + t) * DHH + dh0];
  float ss = ov.x*ov.x + ov.y*ov.y + ov.z*ov.z + ov.w*ov.w;
  #pragma unroll
  for (int off = 8; off > 0; off >>= 1)
    ss += __shfl_xor_sync(0xffffffffu, ss, off, 16);
  float sc = rsqrtf(ss * (1.f / 64.f) + 1e-6f);
  float4 gv = *(const float4*)&g[dh0];
  float ys[4] = { ov.x * sc * gv.x, ov.y * sc * gv.y, ov.z * sc * gv.z, ov.w * sc * gv.w };
  __nv_bfloat16 hh[4], ll[4];
  #pragma unroll
  for (int j = 0; j < 4; j++){
    hh[j] = __float2bfloat16_rn(ys[j]);
    ll[j] = __float2bfloat16_rn(ys[j] - __bfloat162float(hh[j]));
  }
  size_t base = (size_t)m * DD + tid * 4;
  *(__nv_bfloat162*)(YH + base)     = __nv_bfloat162(hh[0], hh[1]);
  *(__nv_bfloat162*)(YH + base + 2) = __nv_bfloat162(hh[2], hh[3]);
  *(__nv_bfloat162*)(YL + base)     = __nv_bfloat162(ll[0], ll[1]);
  *(__nv_bfloat162*)(YL + base + 2) = __nv_bfloat162(ll[2], ll[3]);
}

// ---------------------------------------------------------------------------
// Launch
// ---------------------------------------------------------------------------
extern "C" void kernel_launch(void* const* d_in, const int* in_sizes, int n_in,
                              void* d_out, int out_size)
{
  (void)in_sizes; (void)n_in; (void)out_size;
  const float* x  = (const float*)d_in[0];
  const float* Wq = (const float*)d_in[1];
  const float* Wk = (const float*)d_in[2];
  const float* Wv = (const float*)d_in[3];
  const float* Wb = (const float*)d_in[4];
  const float* cq = (const float*)d_in[5];
  const float* ck = (const float*)d_in[6];
  const float* cv = (const float*)d_in[7];
  const float* rg = (const float*)d_in[8];
  const float* Wo = (const float*)d_in[9];
  float* out = (float*)d_out;

  float *qc, *kc, *vc, *q, *k, *v, *beta, *o;
  __nv_bfloat16 *xh, *xl, *oh, *ol, *wh, *wl;
  cudaGetSymbolAddress((void**)&qc,  g_qc);
  cudaGetSymbolAddress((void**)&kc,  g_kc);
  cudaGetSymbolAddress((void**)&vc,  g_vc);
  cudaGetSymbolAddress((void**)&q,   g_q);
  cudaGetSymbolAddress((void**)&k,   g_k);
  cudaGetSymbolAddress((void**)&v,   g_v);
  cudaGetSymbolAddress((void**)&beta, g_beta);
  cudaGetSymbolAddress((void**)&o,   g_o);
  cudaGetSymbolAddress((void**)&xh,  g_xh);
  cudaGetSymbolAddress((void**)&xl,  g_xl);
  cudaGetSymbolAddress((void**)&oh,  g_oh);
  cudaGetSymbolAddress((void**)&ol,  g_ol);
  cudaGetSymbolAddress((void**)&wh,  g_wh);
  cudaGetSymbolAddress((void**)&wl,  g_wl);

  cudaFuncSetAttribute(gemm_mma, cudaFuncAttributeMaxDynamicSharedMemorySize, GEMM_SMEM);

  const size_t WSZ = (size_t)DD * DD;
  dim3 wgrid(32, 32), wblk(32, 8);
  dim3 ggrid(DD / 128, MM / 128);

  split_kernel<<<MM * DD / 1024, 256>>>(x, xh, xl);
  wsplit_kernel<<<wgrid, wblk>>>(Wq, wh + 0*WSZ, wl + 0*WSZ);
  wsplit_kernel<<<wgrid, wblk>>>(Wk, wh + 1*WSZ, wl + 1*WSZ);
  wsplit_kernel<<<wgrid, wblk>>>(Wv, wh + 2*WSZ, wl + 2*WSZ);
  wsplit_kernel<<<wgrid, wblk>>>(Wo, wh + 3*WSZ, wl + 3*WSZ);

  gemm_mma<<<ggrid, 256, GEMM_SMEM>>>(xh, xl, wh + 0*WSZ, wl + 0*WSZ, qc);
  gemm_mma<<<ggrid, 256, GEMM_SMEM>>>(xh, xl, wh + 1*WSZ, wl + 1*WSZ, kc);
  gemm_mma<<<ggrid, 256, GEMM_SMEM>>>(xh, xl, wh + 2*WSZ, wl + 2*WSZ, vc);

  beta_kernel<<<MM, 64>>>(x, Wb, beta);
  conv_kernel<true ><<<MM, 256>>>(qc, cq, q);
  conv_kernel<true ><<<MM, 256>>>(kc, ck, k);
  conv_kernel<false><<<MM, 256>>>(vc, cv, v);

  scan_kernel<<<BB * HH, 128>>>(q, k, v, beta, o);

  rmsnorm_kernel<<<MM, 256>>>(o, rg, oh, ol);
  gemm_mma<<<ggrid, 256, GEMM_SMEM>>>(oh, ol, wh + 3*WSZ, wl + 3*WSZ, out);
}

// round 6
// speedup vs baseline: 1.7571x; 1.7571x over previous
#include <cuda_runtime.h>
#include <cuda_bf16.h>
#include <cstdint>

// Problem constants
#define BB 2
#define TT 2048
#define DD 1024
#define HH 16
#define DHH 64
#define MM (BB*TT)          // 4096 rows
#define CC 64               // WY chunk length
#define NC (TT/CC)          // 32 chunks per (b,h)
#define NBH (BB*HH)         // 32
#define NCHT (NBH*NC)       // 1024 chunk-heads

// ---------------------------------------------------------------------------
// Scratch (device globals: no runtime allocation allowed)
// ---------------------------------------------------------------------------
__device__ float g_qc[MM*DD];          // x@Wq (pre-conv), [M,D]
__device__ float g_kc[MM*DD];
__device__ float g_vc[MM*DD];
__device__ float g_q [MM*DD];          // post conv/silu/l2norm, [B,H,T,DH]
__device__ float g_k [MM*DD];
__device__ float g_v [MM*DD];
__device__ float g_beta[BB*HH*TT];     // [B,H,T]
__device__ float g_o [MM*DD];          // scan output, [B,H,T,DH]

// WY precomputed per chunk-head: [NCHT][64][64]
__device__ float g_W [NCHT*CC*DHH];
__device__ float g_U0[NCHT*CC*DHH];
__device__ float g_M [NCHT*CC*CC];

// bf16 split operands for tensor-core GEMMs
__device__ __nv_bfloat16 g_xh[MM*DD];
__device__ __nv_bfloat16 g_xl[MM*DD];
__device__ __nv_bfloat16 g_oh[MM*DD];
__device__ __nv_bfloat16 g_ol[MM*DD];
__device__ __nv_bfloat16 g_wh[4][DD*DD]; // W^T hi [N,K]
__device__ __nv_bfloat16 g_wl[4][DD*DD];

// ---------------------------------------------------------------------------
// f32x2 packed helpers (Blackwell FFMA2)
// ---------------------------------------------------------------------------
__device__ __forceinline__ unsigned long long dup2(float x){
  unsigned long long r;
  unsigned u = __float_as_uint(x);
  asm("mov.b64 %0, {%1, %1};" : "=l"(r) : "r"(u));
  return r;
}
__device__ __forceinline__ void ffma2(unsigned long long &c, unsigned long long a, unsigned long long b){
  asm("fma.rn.f32x2 %0, %1, %2, %0;" : "+l"(c) : "l"(a), "l"(b));
}
__device__ __forceinline__ float2 unpk2(unsigned long long p){
  unsigned lo, hi;
  asm("mov.b64 {%0, %1}, %2;" : "=r"(lo), "=r"(hi) : "l"(p));
  return make_float2(__uint_as_float(lo), __uint_as_float(hi));
}

// ---------------------------------------------------------------------------
// smem / cp.async / mma helpers (base compute_103-legal)
// ---------------------------------------------------------------------------
__device__ __forceinline__ uint32_t smem_u32(const void* p){
  uint32_t a;
  asm("{ .reg .u64 t; cvta.to.shared.u64 t, %1; cvt.u32.u64 %0, t; }" : "=r"(a) : "l"(p));
  return a;
}
__device__ __forceinline__ void cpasync16(uint32_t dst, const void* src){
  asm volatile("cp.async.cg.shared.global [%0], [%1], 16;" :: "r"(dst), "l"(src));
}
__device__ __forceinline__ void cpasync_commit(){
  asm volatile("cp.async.commit_group;" ::: "memory");
}
__device__ __forceinline__ void ldm4(uint32_t* r, uint32_t addr){
  asm volatile("ldmatrix.sync.aligned.m8n8.x4.shared.b16 {%0,%1,%2,%3}, [%4];"
               : "=r"(r[0]), "=r"(r[1]), "=r"(r[2]), "=r"(r[3]) : "r"(addr));
}
__device__ __forceinline__ void mma16816(float* d, const uint32_t* a, const uint32_t* b){
  asm volatile(
    "mma.sync.aligned.m16n8k16.row.col.f32.bf16.bf16.f32 "
    "{%0,%1,%2,%3}, {%4,%5,%6,%7}, {%8,%9}, {%0,%1,%2,%3};"
    : "+f"(d[0]), "+f"(d[1]), "+f"(d[2]), "+f"(d[3])
    : "r"(a[0]), "r"(a[1]), "r"(a[2]), "r"(a[3]), "r"(b[0]), "r"(b[1]));
}

// ---------------------------------------------------------------------------
// Tensor-pipe GEMM (unchanged from best 1591us version)
// ---------------------------------------------------------------------------
#define GK   1024
#define KC   32
#define NCHG (GK/KC)
#define ROWB 80
#define MATB (128*ROWB)
#define STAGEB (4*MATB)
#define GEMM_SMEM (2*STAGEB)

__global__ __launch_bounds__(256, 2)
void gemm_mma(const __nv_bfloat16* __restrict__ Ah, const __nv_bfloat16* __restrict__ Al,
              const __nv_bfloat16* __restrict__ Bh, const __nv_bfloat16* __restrict__ Bl,
              float* __restrict__ C)
{
  extern __shared__ char smem[];
  const uint32_t sb = smem_u32(smem);
  const int tid   = threadIdx.x;
  const int wid   = tid >> 5;
  const int lane  = tid & 31;
  const int warpM = wid & 1;
  const int warpN = wid >> 1;
  const int tileM = blockIdx.y * 128;
  const int tileN = blockIdx.x * 128;

  const __nv_bfloat16* gsrc[4] = {
    Ah + (size_t)tileM * GK, Al + (size_t)tileM * GK,
    Bh + (size_t)tileN * GK, Bl + (size_t)tileN * GK };

  auto load_stage = [&](int s, int kt){
    const uint32_t base = sb + s * STAGEB;
    #pragma unroll
    for (int i = 0; i < 8; i++){
      int cid = tid + i * 256;
      int mat = cid >> 9;
      int rem = cid & 511;
      int row = rem >> 2, ch = rem & 3;
      cpasync16(base + mat * MATB + row * ROWB + ch * 16,
                gsrc[mat] + (size_t)row * GK + kt + ch * 8);
    }
  };

  float acc[4][4][4];
  #pragma unroll
  for (int mt = 0; mt < 4; mt++)
    #pragma unroll
    for (int nt = 0; nt < 4; nt++)
      #pragma unroll
      for (int j = 0; j < 4; j++) acc[mt][nt][j] = 0.f;

  const int aRow   = lane & 15;
  const int aKhalf = lane >> 4;
  const uint32_t aOff = (uint32_t)(warpM*64 + aRow) * ROWB + aKhalf * 16;
  const int bRow   = (lane & 7) + ((lane >> 4) << 3);
  const int bKhalf = (lane >> 3) & 1;
  const uint32_t bOff = (uint32_t)(warpN*32 + bRow) * ROWB + bKhalf * 16;

  load_stage(0, 0);  cpasync_commit();
  load_stage(1, KC); cpasync_commit();

  for (int c = 0; c < NCHG; c++){
    if (c < NCHG - 1) asm volatile("cp.async.wait_group 1;" ::: "memory");
    else              asm volatile("cp.async.wait_group 0;" ::: "memory");
    __syncthreads();

    const uint32_t sbuf = sb + (c & 1) * STAGEB;
    #pragma unroll
    for (int ks = 0; ks < 2; ks++){
      const uint32_t koff = ks * 32;
      uint32_t ah[4][4], bh[2][4], bl[2][4];
      #pragma unroll
      for (int mt = 0; mt < 4; mt++)
        ldm4(ah[mt], sbuf + 0*MATB + aOff + mt*16*ROWB + koff);
      #pragma unroll
      for (int p = 0; p < 2; p++)
        ldm4(bh[p], sbuf + 2*MATB + bOff + p*16*ROWB + koff);
      #pragma unroll
      for (int mt = 0; mt < 4; mt++)
        #pragma unroll
        for (int nt = 0; nt < 4; nt++)
          mma16816(acc[mt][nt], ah[mt], &bh[nt>>1][(nt&1)*2]);
      #pragma unroll
      for (int p = 0; p < 2; p++)
        ldm4(bl[p], sbuf + 3*MATB + bOff + p*16*ROWB + koff);
      #pragma unroll
      for (int mt = 0; mt < 4; mt++)
        #pragma unroll
        for (int nt = 0; nt < 4; nt++)
          mma16816(acc[mt][nt], ah[mt], &bl[nt>>1][(nt&1)*2]);
      #pragma unroll
      for (int mt = 0; mt < 4; mt++){
        uint32_t al_[4];
        ldm4(al_, sbuf + 1*MATB + aOff + mt*16*ROWB + koff);
        #pragma unroll
        for (int nt = 0; nt < 4; nt++)
          mma16816(acc[mt][nt], al_, &bh[nt>>1][(nt&1)*2]);
      }
    }
    __syncthreads();
    if (c + 2 < NCHG){ load_stage(c & 1, (c + 2) * KC); cpasync_commit(); }
  }

  const int rBase = tileM + warpM*64 + (lane >> 2);
  const int cBase = tileN + warpN*32 + (lane & 3) * 2;
  #pragma unroll
  for (int mt = 0; mt < 4; mt++){
    #pragma unroll
    for (int nt = 0; nt < 4; nt++){
      float* p0 = C + (size_t)(rBase + mt*16)     * GK + cBase + nt*8;
      float* p1 = C + (size_t)(rBase + mt*16 + 8) * GK + cBase + nt*8;
      *(float2*)p0 = make_float2(acc[mt][nt][0], acc[mt][nt][1]);
      *(float2*)p1 = make_float2(acc[mt][nt][2], acc[mt][nt][3]);
    }
  }
}

// ---------------------------------------------------------------------------
// fp32 -> (hi, lo) bf16 split
// ---------------------------------------------------------------------------
__global__ void split_kernel(const float* __restrict__ X,
                             __nv_bfloat16* __restrict__ H, __nv_bfloat16* __restrict__ L)
{
  int i = (blockIdx.x * 256 + threadIdx.x) * 4;
  float4 xv = *(const float4*)(X + i);
  float xs[4] = {xv.x, xv.y, xv.z, xv.w};
  __nv_bfloat16 h[4], l[4];
  #pragma unroll
  for (int j = 0; j < 4; j++){
    h[j] = __float2bfloat16_rn(xs[j]);
    l[j] = __float2bfloat16_rn(xs[j] - __bfloat162float(h[j]));
  }
  *(__nv_bfloat162*)(H + i)     = __nv_bfloat162(h[0], h[1]);
  *(__nv_bfloat162*)(H + i + 2) = __nv_bfloat162(h[2], h[3]);
  *(__nv_bfloat162*)(L + i)     = __nv_bfloat162(l[0], l[1]);
  *(__nv_bfloat162*)(L + i + 2) = __nv_bfloat162(l[2], l[3]);
}

// ---------------------------------------------------------------------------
// Weight transpose + bf16 split
// ---------------------------------------------------------------------------
__global__ void wsplit_kernel(const float* __restrict__ W,
                              __nv_bfloat16* __restrict__ TH, __nv_bfloat16* __restrict__ TL)
{
  __shared__ float tile[32][33];
  const int n0 = blockIdx.x * 32, k0 = blockIdx.y * 32;
  const int tx = threadIdx.x, ty = threadIdx.y;
  #pragma unroll
  for (int i = 0; i < 4; i++)
    tile[ty + i*8][tx] = W[(size_t)(k0 + ty + i*8) * DD + n0 + tx];
  __syncthreads();
  #pragma unroll
  for (int i = 0; i < 4; i++){
    float v = tile[tx][ty + i*8];
    __nv_bfloat16 h = __float2bfloat16_rn(v);
    __nv_bfloat16 l = __float2bfloat16_rn(v - __bfloat162float(h));
    size_t idx = (size_t)(n0 + ty + i*8) * DD + k0 + tx;
    TH[idx] = h; TL[idx] = l;
  }
}

// ---------------------------------------------------------------------------
// beta = sigmoid(x @ Wb)
// ---------------------------------------------------------------------------
__global__ void beta_kernel(const float* __restrict__ x, const float* __restrict__ Wb,
                            float* __restrict__ gb)
{
  const int m = blockIdx.x;
  const int tid = threadIdx.x;
  const int h = tid & 15, part = tid >> 4;
  __shared__ float sx[DD];
  for (int i = tid; i < DD/4; i += 64)
    *(float4*)&sx[i*4] = *(const float4*)&x[(size_t)m * DD + i*4];
  __syncthreads();
  float acc = 0.f;
  const int kbase = part * 256;
  for (int kk = 0; kk < 256; kk++)
    acc += sx[kbase + kk] * Wb[(size_t)(kbase + kk) * HH + h];
  __shared__ float red[64];
  red[tid] = acc;
  __syncthreads();
  if (tid < 16) {
    float s = red[tid] + red[tid+16] + red[tid+32] + red[tid+48];
    int b = m >> 11, t = m & (TT-1);
    gb[((size_t)b * HH + tid) * TT + t] = 1.f / (1.f + __expf(-s));
  }
}

// ---------------------------------------------------------------------------
// Causal depthwise conv (K=4) + SiLU (+ optional L2 norm), [M,D] -> [B,H,T,DH]
// ---------------------------------------------------------------------------
template<bool NORM>
__global__ void conv_kernel(const float* __restrict__ X, const float* __restrict__ W,
                            float* __restrict__ Y)
{
  const int m = blockIdx.x;
  const int b = m >> 11, t = m & (TT-1);
  const int tid = threadIdx.x;
  const int c0 = tid * 4;

  float warr[4][4];
  #pragma unroll
  for (int j = 0; j < 4; j++) {
    float4 wv = *(const float4*)&W[(size_t)(c0 + j) * 4];
    warr[j][0] = wv.x; warr[j][1] = wv.y; warr[j][2] = wv.z; warr[j][3] = wv.w;
  }
  float acc[4] = {0.f, 0.f, 0.f, 0.f};
  #pragma unroll
  for (int i = 0; i < 4; i++) {
    int tt = t - 3 + i;
    if (tt >= 0) {
      float4 xv = *(const float4*)&X[((size_t)(b * TT + tt)) * DD + c0];
      acc[0] += warr[0][i] * xv.x;
      acc[1] += warr[1][i] * xv.y;
      acc[2] += warr[2][i] * xv.z;
      acc[3] += warr[3][i] * xv.w;
    }
  }
  float y[4];
  #pragma unroll
  for (int j = 0; j < 4; j++) {
    float s = 1.f / (1.f + __expf(-acc[j]));
    y[j] = acc[j] * s;
  }
  float scale = 1.f;
  if (NORM) {
    float ss = y[0]*y[0] + y[1]*y[1] + y[2]*y[2] + y[3]*y[3];
    #pragma unroll
    for (int off = 8; off > 0; off >>= 1)
      ss += __shfl_xor_sync(0xffffffffu, ss, off, 16);
    scale = rsqrtf(ss + 1e-6f);
  }
  const int h = tid >> 4;
  const int dh0 = (tid & 15) * 4;
  *(float4*)&Y[(((size_t)(b * HH + h)) * TT + t) * DHH + dh0] =
      make_float4(y[0]*scale, y[1]*scale, y[2]*scale, y[3]*scale);
}

// ---------------------------------------------------------------------------
// WY precompute: per chunk-head, A = strict_tril(diag(b) K K^T),
// Tinv = (I+A)^-1, W = Tinv diag(b) K, U0 = Tinv diag(b) V, M = tril(Q K^T, 0).
// One CTA per (bh, chunk). 256 threads.
// smem floats: K[4096] V[4096] Q[4096] Kt[64*68] A[4096] Ti[64*65] B[64]
// ---------------------------------------------------------------------------
#define PRE_K  0
#define PRE_V  4096
#define PRE_Q  8192
#define PRE_KT 12288          // pitch 68
#define PRE_A  16640
#define PRE_TI 20736          // pitch 65
#define PRE_B  24896
#define PRE_TOT 24960         // floats -> 99840 bytes

__global__ __launch_bounds__(256, 1)
void wy_pre(const float* __restrict__ gq, const float* __restrict__ gk,
            const float* __restrict__ gv, const float* __restrict__ gb,
            float* __restrict__ gW, float* __restrict__ gU0, float* __restrict__ gM)
{
  extern __shared__ float sm[];
  const int chunk = blockIdx.x;
  const int bh    = blockIdx.y;
  const int cid   = bh * NC + chunk;
  const int tid   = threadIdx.x;

  const float* K = gk + ((size_t)bh * TT + chunk * CC) * DHH;
  const float* Q = gq + ((size_t)bh * TT + chunk * CC) * DHH;
  const float* V = gv + ((size_t)bh * TT + chunk * CC) * DHH;
  const float* B = gb + (size_t)bh * TT + chunk * CC;

  // load K (also transposed), Q, V, beta
  #pragma unroll
  for (int i = 0; i < 4; i++){
    int idx  = tid + i * 256;       // 0..1023 float4 units
    int row  = idx >> 4, c4 = idx & 15;
    float4 kv = *(const float4*)&K[row * DHH + c4 * 4];
    *(float4*)&sm[PRE_K + row * 64 + c4 * 4] = kv;
    sm[PRE_KT + (c4*4+0) * 68 + row] = kv.x;
    sm[PRE_KT + (c4*4+1) * 68 + row] = kv.y;
    sm[PRE_KT + (c4*4+2) * 68 + row] = kv.z;
    sm[PRE_KT + (c4*4+3) * 68 + row] = kv.w;
    *(float4*)&sm[PRE_Q + row * 64 + c4 * 4] = *(const float4*)&Q[row * DHH + c4 * 4];
    *(float4*)&sm[PRE_V + row * 64 + c4 * 4] = *(const float4*)&V[row * DHH + c4 * 4];
  }
  if (tid < 64) sm[PRE_B + tid] = B[tid];
  // zero Ti
  for (int i = tid; i < 64*65; i += 256) sm[PRE_TI + i] = 0.f;
  __syncthreads();

  // A = K K^T (strict lower, *b_t); M = Q K^T (incl lower) -> global
  {
    const int ty = tid >> 4, tx = tid & 15;
    const int r0 = ty * 4, c0 = tx * 4;
    unsigned long long accA[4][2], accM[4][2];
    #pragma unroll
    for (int m = 0; m < 4; m++){ accA[m][0]=accA[m][1]=accM[m][0]=accM[m][1]=0ull; }
    #pragma unroll 8
    for (int d = 0; d < 64; d++){
      ulonglong2 kc = *(const ulonglong2*)&sm[PRE_KT + d * 68 + c0];
      #pragma unroll
      for (int m = 0; m < 4; m++){
        unsigned long long kr = dup2(sm[PRE_K + (r0+m)*64 + d]);
        unsigned long long qr = dup2(sm[PRE_Q + (r0+m)*64 + d]);
        ffma2(accA[m][0], kr, kc.x);  ffma2(accA[m][1], kr, kc.y);
        ffma2(accM[m][0], qr, kc.x);  ffma2(accM[m][1], qr, kc.y);
      }
    }
    float* Mout = gM + (size_t)cid * (CC*CC);
    #pragma unroll
    for (int m = 0; m < 4; m++){
      const int t = r0 + m;
      const float bt = sm[PRE_B + t];
      float2 a01 = unpk2(accA[m][0]), a23 = unpk2(accA[m][1]);
      float2 m01 = unpk2(accM[m][0]), m23 = unpk2(accM[m][1]);
      float av[4] = {a01.x, a01.y, a23.x, a23.y};
      float mv[4] = {m01.x, m01.y, m23.x, m23.y};
      #pragma unroll
      for (int i = 0; i < 4; i++){
        const int s = c0 + i;
        sm[PRE_A + t*64 + s] = (s < t) ? bt * av[i] : 0.f;
        Mout[t*64 + s]       = (s <= t) ? mv[i] : 0.f;
      }
    }
  }
  __syncthreads();

  // Tinv: column-private forward substitution (lane c owns column c)
  if (tid < 64){
    const int c = tid;
    sm[PRE_TI + c*65 + c] = 1.f;
    for (int t = c + 1; t < 64; t++){
      float acc = 0.f;
      for (int j = c; j < t; j++)
        acc += sm[PRE_A + t*64 + j] * sm[PRE_TI + j*65 + c];
      sm[PRE_TI + t*65 + c] = -acc;
    }
  }
  __syncthreads();

  // W = Tinv diag(b) K, U0 = Tinv diag(b) V
  {
    const int ty = tid >> 4, tx = tid & 15;
    const int r0 = ty * 4, c0 = tx * 4;
    unsigned long long accW[4][2], accU[4][2];
    #pragma unroll
    for (int m = 0; m < 4; m++){ accW[m][0]=accW[m][1]=accU[m][0]=accU[m][1]=0ull; }
    #pragma unroll 8
    for (int j = 0; j < 64; j++){
      const float bj = sm[PRE_B + j];
      ulonglong2 k2 = *(const ulonglong2*)&sm[PRE_K + j*64 + c0];
      ulonglong2 v2 = *(const ulonglong2*)&sm[PRE_V + j*64 + c0];
      #pragma unroll
      for (int m = 0; m < 4; m++){
        unsigned long long tb = dup2(sm[PRE_TI + (r0+m)*65 + j] * bj);
        ffma2(accW[m][0], tb, k2.x);  ffma2(accW[m][1], tb, k2.y);
        ffma2(accU[m][0], tb, v2.x);  ffma2(accU[m][1], tb, v2.y);
      }
    }
    float* Wout = gW  + (size_t)cid * (CC*DHH);
    float* Uout = gU0 + (size_t)cid * (CC*DHH);
    #pragma unroll
    for (int m = 0; m < 4; m++){
      const int t = r0 + m;
      float2 w01 = unpk2(accW[m][0]), w23 = unpk2(accW[m][1]);
      float2 u01 = unpk2(accU[m][0]), u23 = unpk2(accU[m][1]);
      *(float4*)&Wout[t*64 + c0] = make_float4(w01.x, w01.y, w23.x, w23.y);
      *(float4*)&Uout[t*64 + c0] = make_float4(u01.x, u01.y, u23.x, u23.y);
    }
  }
}

// ---------------------------------------------------------------------------
// WY sequential pass. Grid (4 vsplits, 32 bh). Each CTA owns 16 v-columns of S.
// Per chunk: U = U0 - W S ; O = Q S + M U ; S += K^T U.
// ---------------------------------------------------------------------------
#define SP 20   // smem pitch (floats) for 16-wide rows, conflict-free

__global__ __launch_bounds__(256, 1)
void wy_seq(const float* __restrict__ gq, const float* __restrict__ gk,
            const float* __restrict__ gW, const float* __restrict__ gU0,
            const float* __restrict__ gM, float* __restrict__ go)
{
  const int vsplit = blockIdx.x;         // 0..3
  const int bh     = blockIdx.y;         // 0..31
  const int colb   = vsplit * 16;
  const int tid    = threadIdx.x;
  const int trow   = tid >> 2;           // 0..63
  const int vg     = tid & 3;
  const int vo     = vg * 4;

  __shared__ __align__(16) float sS[64 * SP];
  __shared__ __align__(16) float sU[64 * SP];

  // zero S
  for (int i = tid; i < 64 * SP; i += 256) sS[i] = 0.f;
  __syncthreads();

  for (int c = 0; c < NC; c++){
    const size_t cid = (size_t)bh * NC + c;
    const float* Wp  = gW  + cid * (CC*DHH);
    const float* U0p = gU0 + cid * (CC*DHH);
    const float* Mp  = gM  + cid * (CC*CC);
    const float* Kp  = gk + ((size_t)bh * TT + c * CC) * DHH;
    const float* Qp  = gq + ((size_t)bh * TT + c * CC) * DHH;
    float*       Op  = go + ((size_t)bh * TT + c * CC) * DHH + colb;

    // phase 1: U = U0 - W S   (thread: row trow, 4 v-cols)
    {
      float4 u0 = *(const float4*)&U0p[trow*64 + colb + vo];
      unsigned long long a0, a1;
      { unsigned lo0=__float_as_uint(u0.x), hi0=__float_as_uint(u0.y);
        unsigned lo1=__float_as_uint(u0.z), hi1=__float_as_uint(u0.w);
        asm("mov.b64 %0, {%1, %2};" : "=l"(a0) : "r"(lo0), "r"(hi0));
        asm("mov.b64 %0, {%1, %2};" : "=l"(a1) : "r"(lo1), "r"(hi1)); }
      #pragma unroll 8
      for (int kk = 0; kk < 64; kk++){
        unsigned long long nw = dup2(-Wp[trow*64 + kk]);
        ulonglong2 s2 = *(const ulonglong2*)&sS[kk*SP + vo];
        ffma2(a0, nw, s2.x);  ffma2(a1, nw, s2.y);
      }
      *(ulonglong2*)&sU[trow*SP + vo] = make_ulonglong2(a0, a1);
    }
    __syncthreads();

    // phase 2: O = Q S + M U  (reads sS, sU; writes global)
    {
      unsigned long long a0 = 0ull, a1 = 0ull;
      #pragma unroll 8
      for (int j = 0; j < 64; j++){
        unsigned long long qd = dup2(Qp[trow*64 + j]);
        ulonglong2 s2 = *(const ulonglong2*)&sS[j*SP + vo];
        ffma2(a0, qd, s2.x);  ffma2(a1, qd, s2.y);
      }
      #pragma unroll 8
      for (int s = 0; s < 64; s++){
        unsigned long long md = dup2(Mp[trow*64 + s]);
        ulonglong2 u2 = *(const ulonglong2*)&sU[s*SP + vo];
        ffma2(a0, md, u2.x);  ffma2(a1, md, u2.y);
      }
      float2 o01 = unpk2(a0), o23 = unpk2(a1);
      *(float4*)&Op[trow*64 + vo] = make_float4(o01.x, o01.y, o23.x, o23.y);
    }
    __syncthreads();

    // phase 3: S += K^T U  (thread: S-row trow(kappa), 4 v-cols)
    {
      ulonglong2 sacc = *(const ulonglong2*)&sS[trow*SP + vo];
      unsigned long long a0 = sacc.x, a1 = sacc.y;
      #pragma unroll 8
      for (int t = 0; t < 64; t++){
        unsigned long long kd = dup2(Kp[t*64 + trow]);
        ulonglong2 u2 = *(const ulonglong2*)&sU[t*SP + vo];
        ffma2(a0, kd, u2.x);  ffma2(a1, kd, u2.y);
      }
      *(ulonglong2*)&sS[trow*SP + vo] = make_ulonglong2(a0, a1);
    }
    __syncthreads();
  }
}

// ---------------------------------------------------------------------------
// Per-head RMSNorm * rms_g, transpose [B,H,T,DH] -> [M,D], bf16 hi/lo split out
// ---------------------------------------------------------------------------
__global__ void rmsnorm_kernel(const float* __restrict__ O, const float* __restrict__ g,
                               __nv_bfloat16* __restrict__ YH, __nv_bfloat16* __restrict__ YL)
{
  const int m = blockIdx.x;
  const int b = m >> 11, t = m & (TT-1);
  const int tid = threadIdx.x;
  const int h = tid >> 4;
  const int dh0 = (tid & 15) * 4;

  float4 ov = *(const float4*)&O[(((size_t)(b * HH + h)) * TT + t) * DHH + dh0];
  float ss = ov.x*ov.x + ov.y*ov.y + ov.z*ov.z + ov.w*ov.w;
  #pragma unroll
  for (int off = 8; off > 0; off >>= 1)
    ss += __shfl_xor_sync(0xffffffffu, ss, off, 16);
  float sc = rsqrtf(ss * (1.f / 64.f) + 1e-6f);
  float4 gv = *(const float4*)&g[dh0];
  float ys[4] = { ov.x * sc * gv.x, ov.y * sc * gv.y, ov.z * sc * gv.z, ov.w * sc * gv.w };
  __nv_bfloat16 hh[4], ll[4];
  #pragma unroll
  for (int j = 0; j < 4; j++){
    hh[j] = __float2bfloat16_rn(ys[j]);
    ll[j] = __float2bfloat16_rn(ys[j] - __bfloat162float(hh[j]));
  }
  size_t base = (size_t)m * DD + tid * 4;
  *(__nv_bfloat162*)(YH + base)     = __nv_bfloat162(hh[0], hh[1]);
  *(__nv_bfloat162*)(YH + base + 2) = __nv_bfloat162(hh[2], hh[3]);
  *(__nv_bfloat162*)(YL + base)     = __nv_bfloat162(ll[0], ll[1]);
  *(__nv_bfloat162*)(YL + base + 2) = __nv_bfloat162(ll[2], ll[3]);
}

// ---------------------------------------------------------------------------
// Launch
// ---------------------------------------------------------------------------
extern "C" void kernel_launch(void* const* d_in, const int* in_sizes, int n_in,
                              void* d_out, int out_size)
{
  (void)in_sizes; (void)n_in; (void)out_size;
  const float* x  = (const float*)d_in[0];
  const float* Wq = (const float*)d_in[1];
  const float* Wk = (const float*)d_in[2];
  const float* Wv = (const float*)d_in[3];
  const float* Wb = (const float*)d_in[4];
  const float* cq = (const float*)d_in[5];
  const float* ck = (const float*)d_in[6];
  const float* cv = (const float*)d_in[7];
  const float* rg = (const float*)d_in[8];
  const float* Wo = (const float*)d_in[9];
  float* out = (float*)d_out;

  float *qc, *kc, *vc, *q, *k, *v, *beta, *o, *gW, *gU0, *gM;
  __nv_bfloat16 *xh, *xl, *oh, *ol, *wh, *wl;
  cudaGetSymbolAddress((void**)&qc,  g_qc);
  cudaGetSymbolAddress((void**)&kc,  g_kc);
  cudaGetSymbolAddress((void**)&vc,  g_vc);
  cudaGetSymbolAddress((void**)&q,   g_q);
  cudaGetSymbolAddress((void**)&k,   g_k);
  cudaGetSymbolAddress((void**)&v,   g_v);
  cudaGetSymbolAddress((void**)&beta, g_beta);
  cudaGetSymbolAddress((void**)&o,   g_o);
  cudaGetSymbolAddress((void**)&gW,  g_W);
  cudaGetSymbolAddress((void**)&gU0, g_U0);
  cudaGetSymbolAddress((void**)&gM,  g_M);
  cudaGetSymbolAddress((void**)&xh,  g_xh);
  cudaGetSymbolAddress((void**)&xl,  g_xl);
  cudaGetSymbolAddress((void**)&oh,  g_oh);
  cudaGetSymbolAddress((void**)&ol,  g_ol);
  cudaGetSymbolAddress((void**)&wh,  g_wh);
  cudaGetSymbolAddress((void**)&wl,  g_wl);

  cudaFuncSetAttribute(gemm_mma, cudaFuncAttributeMaxDynamicSharedMemorySize, GEMM_SMEM);
  cudaFuncSetAttribute(wy_pre,   cudaFuncAttributeMaxDynamicSharedMemorySize, PRE_TOT * 4);

  const size_t WSZ = (size_t)DD * DD;
  dim3 wgrid(32, 32), wblk(32, 8);
  dim3 ggrid(DD / 128, MM / 128);

  split_kernel<<<MM * DD / 1024, 256>>>(x, xh, xl);
  wsplit_kernel<<<wgrid, wblk>>>(Wq, wh + 0*WSZ, wl + 0*WSZ);
  wsplit_kernel<<<wgrid, wblk>>>(Wk, wh + 1*WSZ, wl + 1*WSZ);
  wsplit_kernel<<<wgrid, wblk>>>(Wv, wh + 2*WSZ, wl + 2*WSZ);
  wsplit_kernel<<<wgrid, wblk>>>(Wo, wh + 3*WSZ, wl + 3*WSZ);

  gemm_mma<<<ggrid, 256, GEMM_SMEM>>>(xh, xl, wh + 0*WSZ, wl + 0*WSZ, qc);
  gemm_mma<<<ggrid, 256, GEMM_SMEM>>>(xh, xl, wh + 1*WSZ, wl + 1*WSZ, kc);
  gemm_mma<<<ggrid, 256, GEMM_SMEM>>>(xh, xl, wh + 2*WSZ, wl + 2*WSZ, vc);

  beta_kernel<<<MM, 64>>>(x, Wb, beta);
  conv_kernel<true ><<<MM, 256>>>(qc, cq, q);
  conv_kernel<true ><<<MM, 256>>>(kc, ck, k);
  conv_kernel<false><<<MM, 256>>>(vc, cv, v);

  wy_pre<<<dim3(NC, NBH), 256, PRE_TOT * 4>>>(q, k, v, beta, gW, gU0, gM);
  wy_seq<<<dim3(4, NBH), 256>>>(q, k, gW, gU0, gM, o);

  rmsnorm_kernel<<<MM, 256>>>(o, rg, oh, ol);
  gemm_mma<<<ggrid, 256, GEMM_SMEM>>>(oh, ol, wh + 3*WSZ, wl + 3*WSZ, out);
}

// round 8
// speedup vs baseline: 2.0342x; 1.1577x over previous
#include <cuda_runtime.h>
#include <cuda_fp16.h>
#include <cstdint>

// Problem constants
#define BB 2
#define TT 2048
#define DD 1024
#define HH 16
#define DHH 64
#define MM (BB*TT)          // 4096 rows
#define CC 64               // WY chunk length
#define NC (TT/CC)          // 32 chunks per (b,h)
#define NBH (BB*HH)         // 32
#define NCHT (NBH*NC)       // 1024 chunk-heads

// ---------------------------------------------------------------------------
// Scratch (device globals: no runtime allocation allowed)
// ---------------------------------------------------------------------------
__device__ float g_qc[MM*DD];          // x@Wq (pre-conv), [M,D]
__device__ float g_kc[MM*DD];
__device__ float g_vc[MM*DD];
__device__ float g_q [MM*DD];          // post conv/silu/l2norm, [B,H,T,DH]
__device__ float g_k [MM*DD];
__device__ float g_v [MM*DD];
__device__ float g_beta[BB*HH*TT];     // [B,H,T]
__device__ float g_o [MM*DD];          // scan output, [B,H,T,DH]

// WY precomputed per chunk-head: [NCHT][64][64]
__device__ float g_W [NCHT*CC*DHH];
__device__ float g_U0[NCHT*CC*DHH];
__device__ float g_M [NCHT*CC*CC];

// fp16 operands for tensor-core GEMMs (single product, no split)
__device__ __half g_xh[MM*DD];         // x fp16, [M,K]
__device__ __half g_oh[MM*DD];         // rmsnormed output fp16, [M,K]
__device__ __half g_wt[4][DD*DD];      // W^T fp16 [N,K] for Wq,Wk,Wv,Wo

// ---------------------------------------------------------------------------
// f32x2 packed helpers (Blackwell FFMA2)
// ---------------------------------------------------------------------------
__device__ __forceinline__ unsigned long long dup2(float x){
  unsigned long long r;
  unsigned u = __float_as_uint(x);
  asm("mov.b64 %0, {%1, %1};" : "=l"(r) : "r"(u));
  return r;
}
__device__ __forceinline__ void ffma2(unsigned long long &c, unsigned long long a, unsigned long long b){
  asm("fma.rn.f32x2 %0, %1, %2, %0;" : "+l"(c) : "l"(a), "l"(b));
}
__device__ __forceinline__ float2 unpk2(unsigned long long p){
  unsigned lo, hi;
  asm("mov.b64 {%0, %1}, %2;" : "=r"(lo), "=r"(hi) : "l"(p));
  return make_float2(__uint_as_float(lo), __uint_as_float(hi));
}

// ---------------------------------------------------------------------------
// smem / cp.async / mma helpers (base compute_103-legal)
// ---------------------------------------------------------------------------
__device__ __forceinline__ uint32_t smem_u32(const void* p){
  uint32_t a;
  asm("{ .reg .u64 t; cvta.to.shared.u64 t, %1; cvt.u32.u64 %0, t; }" : "=r"(a) : "l"(p));
  return a;
}
__device__ __forceinline__ void cpasync16(uint32_t dst, const void* src){
  asm volatile("cp.async.cg.shared.global [%0], [%1], 16;" :: "r"(dst), "l"(src));
}
__device__ __forceinline__ void cpasync_commit(){
  asm volatile("cp.async.commit_group;" ::: "memory");
}
__device__ __forceinline__ void ldm4(uint32_t* r, uint32_t addr){
  asm volatile("ldmatrix.sync.aligned.m8n8.x4.shared.b16 {%0,%1,%2,%3}, [%4];"
               : "=r"(r[0]), "=r"(r[1]), "=r"(r[2]), "=r"(r[3]) : "r"(addr));
}
__device__ __forceinline__ void mma16816h(float* d, const uint32_t* a, const uint32_t* b){
  asm volatile(
    "mma.sync.aligned.m16n8k16.row.col.f32.f16.f16.f32 "
    "{%0,%1,%2,%3}, {%4,%5,%6,%7}, {%8,%9}, {%0,%1,%2,%3};"
    : "+f"(d[0]), "+f"(d[1]), "+f"(d[2]), "+f"(d[3])
    : "r"(a[0]), "r"(a[1]), "r"(a[2]), "r"(a[3]), "r"(b[0]), "r"(b[1]));
}

// ---------------------------------------------------------------------------
// fp16 tensor-pipe GEMM: C[M,1024] = A[M,1024] @ B^T, B stored [N,K] K-major.
// Single product. Tile 128x128, K-chunk 32, 2-stage cp.async.
// 8 warps = 2(M) x 4(N); warp tile 64x32.
// ---------------------------------------------------------------------------
#define GK   1024
#define KC   32
#define NCHG (GK/KC)
#define ROWB 80                // 32 fp16 (64B) + 16B pad
#define MATB (128*ROWB)        // 10240
#define STAGEB (2*MATB)        // A,B = 20480
#define GEMM_SMEM (2*STAGEB)   // 40960

__global__ __launch_bounds__(256, 2)
void gemm_mma(const __half* __restrict__ A, const __half* __restrict__ B,
              float* __restrict__ C)
{
  extern __shared__ char smem[];
  const uint32_t sb = smem_u32(smem);
  const int tid   = threadIdx.x;
  const int wid   = tid >> 5;
  const int lane  = tid & 31;
  const int warpM = wid & 1;
  const int warpN = wid >> 1;
  const int tileM = blockIdx.y * 128;
  const int tileN = blockIdx.x * 128;

  const __half* gsrc[2] = { A + (size_t)tileM * GK, B + (size_t)tileN * GK };

  // loader: 2 matrices x 128 rows x 4 chunks(16B) = 1024 chunks, 4 per thread
  auto load_stage = [&](int s, int kt){
    const uint32_t base = sb + s * STAGEB;
    #pragma unroll
    for (int i = 0; i < 4; i++){
      int cid = tid + i * 256;
      int mat = cid >> 9;
      int rem = cid & 511;
      int row = rem >> 2, ch = rem & 3;
      cpasync16(base + mat * MATB + row * ROWB + ch * 16,
                gsrc[mat] + (size_t)row * GK + kt + ch * 8);
    }
  };

  float acc[4][4][4];
  #pragma unroll
  for (int mt = 0; mt < 4; mt++)
    #pragma unroll
    for (int nt = 0; nt < 4; nt++)
      #pragma unroll
      for (int j = 0; j < 4; j++) acc[mt][nt][j] = 0.f;

  const int aRow   = lane & 15;
  const int aKhalf = lane >> 4;
  const uint32_t aOff = (uint32_t)(warpM*64 + aRow) * ROWB + aKhalf * 16;
  const int bRow   = (lane & 7) + ((lane >> 4) << 3);
  const int bKhalf = (lane >> 3) & 1;
  const uint32_t bOff = (uint32_t)(warpN*32 + bRow) * ROWB + bKhalf * 16;

  load_stage(0, 0);  cpasync_commit();
  load_stage(1, KC); cpasync_commit();

  for (int c = 0; c < NCHG; c++){
    if (c < NCHG - 1) asm volatile("cp.async.wait_group 1;" ::: "memory");
    else              asm volatile("cp.async.wait_group 0;" ::: "memory");
    __syncthreads();

    const uint32_t sbuf = sb + (c & 1) * STAGEB;
    #pragma unroll
    for (int ks = 0; ks < 2; ks++){
      const uint32_t koff = ks * 32;
      uint32_t ar[4][4], br[2][4];
      #pragma unroll
      for (int mt = 0; mt < 4; mt++)
        ldm4(ar[mt], sbuf + 0*MATB + aOff + mt*16*ROWB + koff);
      #pragma unroll
      for (int p = 0; p < 2; p++)
        ldm4(br[p], sbuf + 1*MATB + bOff + p*16*ROWB + koff);
      #pragma unroll
      for (int mt = 0; mt < 4; mt++)
        #pragma unroll
        for (int nt = 0; nt < 4; nt++)
          mma16816h(acc[mt][nt], ar[mt], &br[nt>>1][(nt&1)*2]);
    }
    __syncthreads();
    if (c + 2 < NCHG){ load_stage(c & 1, (c + 2) * KC); cpasync_commit(); }
  }

  const int rBase = tileM + warpM*64 + (lane >> 2);
  const int cBase = tileN + warpN*32 + (lane & 3) * 2;
  #pragma unroll
  for (int mt = 0; mt < 4; mt++){
    #pragma unroll
    for (int nt = 0; nt < 4; nt++){
      float* p0 = C + (size_t)(rBase + mt*16)     * GK + cBase + nt*8;
      float* p1 = C + (size_t)(rBase + mt*16 + 8) * GK + cBase + nt*8;
      *(float2*)p0 = make_float2(acc[mt][nt][0], acc[mt][nt][1]);
      *(float2*)p1 = make_float2(acc[mt][nt][2], acc[mt][nt][3]);
    }
  }
}

// ---------------------------------------------------------------------------
// fp32 -> fp16
// ---------------------------------------------------------------------------
__global__ void tohalf_kernel(const float* __restrict__ X, __half* __restrict__ H)
{
  int i = (blockIdx.x * 256 + threadIdx.x) * 4;
  float4 xv = *(const float4*)(X + i);
  __half2 h0 = __floats2half2_rn(xv.x, xv.y);
  __half2 h1 = __floats2half2_rn(xv.z, xv.w);
  *(__half2*)(H + i)     = h0;
  *(__half2*)(H + i + 2) = h1;
}

// ---------------------------------------------------------------------------
// Weight transpose + fp16: W[K,N] fp32 -> Wt [N,K] fp16
// ---------------------------------------------------------------------------
__global__ void wt_kernel(const float* __restrict__ W, __half* __restrict__ TH)
{
  __shared__ float tile[32][33];
  const int n0 = blockIdx.x * 32, k0 = blockIdx.y * 32;
  const int tx = threadIdx.x, ty = threadIdx.y;
  #pragma unroll
  for (int i = 0; i < 4; i++)
    tile[ty + i*8][tx] = W[(size_t)(k0 + ty + i*8) * DD + n0 + tx];
  __syncthreads();
  #pragma unroll
  for (int i = 0; i < 4; i++){
    float v = tile[tx][ty + i*8];
    TH[(size_t)(n0 + ty + i*8) * DD + k0 + tx] = __float2half_rn(v);
  }
}

// ---------------------------------------------------------------------------
// beta = sigmoid(x @ Wb)
// ---------------------------------------------------------------------------
__global__ void beta_kernel(const float* __restrict__ x, const float* __restrict__ Wb,
                            float* __restrict__ gb)
{
  const int m = blockIdx.x;
  const int tid = threadIdx.x;
  const int h = tid & 15, part = tid >> 4;
  __shared__ float sx[DD];
  for (int i = tid; i < DD/4; i += 64)
    *(float4*)&sx[i*4] = *(const float4*)&x[(size_t)m * DD + i*4];
  __syncthreads();
  float acc = 0.f;
  const int kbase = part * 256;
  for (int kk = 0; kk < 256; kk++)
    acc += sx[kbase + kk] * Wb[(size_t)(kbase + kk) * HH + h];
  __shared__ float red[64];
  red[tid] = acc;
  __syncthreads();
  if (tid < 16) {
    float s = red[tid] + red[tid+16] + red[tid+32] + red[tid+48];
    int b = m >> 11, t = m & (TT-1);
    gb[((size_t)b * HH + tid) * TT + t] = 1.f / (1.f + __expf(-s));
  }
}

// ---------------------------------------------------------------------------
// Causal depthwise conv (K=4) + SiLU (+ optional L2 norm), [M,D] -> [B,H,T,DH]
// ---------------------------------------------------------------------------
template<bool NORM>
__global__ void conv_kernel(const float* __restrict__ X, const float* __restrict__ W,
                            float* __restrict__ Y)
{
  const int m = blockIdx.x;
  const int b = m >> 11, t = m & (TT-1);
  const int tid = threadIdx.x;
  const int c0 = tid * 4;

  float warr[4][4];
  #pragma unroll
  for (int j = 0; j < 4; j++) {
    float4 wv = *(const float4*)&W[(size_t)(c0 + j) * 4];
    warr[j][0] = wv.x; warr[j][1] = wv.y; warr[j][2] = wv.z; warr[j][3] = wv.w;
  }
  float acc[4] = {0.f, 0.f, 0.f, 0.f};
  #pragma unroll
  for (int i = 0; i < 4; i++) {
    int tt = t - 3 + i;
    if (tt >= 0) {
      float4 xv = *(const float4*)&X[((size_t)(b * TT + tt)) * DD + c0];
      acc[0] += warr[0][i] * xv.x;
      acc[1] += warr[1][i] * xv.y;
      acc[2] += warr[2][i] * xv.z;
      acc[3] += warr[3][i] * xv.w;
    }
  }
  float y[4];
  #pragma unroll
  for (int j = 0; j < 4; j++) {
    float s = 1.f / (1.f + __expf(-acc[j]));
    y[j] = acc[j] * s;
  }
  float scale = 1.f;
  if (NORM) {
    float ss = y[0]*y[0] + y[1]*y[1] + y[2]*y[2] + y[3]*y[3];
    #pragma unroll
    for (int off = 8; off > 0; off >>= 1)
      ss += __shfl_xor_sync(0xffffffffu, ss, off, 16);
    scale = rsqrtf(ss + 1e-6f);
  }
  const int h = tid >> 4;
  const int dh0 = (tid & 15) * 4;
  *(float4*)&Y[(((size_t)(b * HH + h)) * TT + t) * DHH + dh0] =
      make_float4(y[0]*scale, y[1]*scale, y[2]*scale, y[3]*scale);
}

// ---------------------------------------------------------------------------
// WY precompute (unchanged from R5)
// ---------------------------------------------------------------------------
#define PRE_K  0
#define PRE_V  4096
#define PRE_Q  8192
#define PRE_KT 12288          // pitch 68
#define PRE_A  16640
#define PRE_TI 20736          // pitch 65
#define PRE_B  24896
#define PRE_TOT 24960

__global__ __launch_bounds__(256, 1)
void wy_pre(const float* __restrict__ gq, const float* __restrict__ gk,
            const float* __restrict__ gv, const float* __restrict__ gb,
            float* __restrict__ gW, float* __restrict__ gU0, float* __restrict__ gM)
{
  extern __shared__ float sm[];
  const int chunk = blockIdx.x;
  const int bh    = blockIdx.y;
  const int cid   = bh * NC + chunk;
  const int tid   = threadIdx.x;

  const float* K = gk + ((size_t)bh * TT + chunk * CC) * DHH;
  const float* Q = gq + ((size_t)bh * TT + chunk * CC) * DHH;
  const float* V = gv + ((size_t)bh * TT + chunk * CC) * DHH;
  const float* B = gb + (size_t)bh * TT + chunk * CC;

  #pragma unroll
  for (int i = 0; i < 4; i++){
    int idx  = tid + i * 256;
    int row  = idx >> 4, c4 = idx & 15;
    float4 kv = *(const float4*)&K[row * DHH + c4 * 4];
    *(float4*)&sm[PRE_K + row * 64 + c4 * 4] = kv;
    sm[PRE_KT + (c4*4+0) * 68 + row] = kv.x;
    sm[PRE_KT + (c4*4+1) * 68 + row] = kv.y;
    sm[PRE_KT + (c4*4+2) * 68 + row] = kv.z;
    sm[PRE_KT + (c4*4+3) * 68 + row] = kv.w;
    *(float4*)&sm[PRE_Q + row * 64 + c4 * 4] = *(const float4*)&Q[row * DHH + c4 * 4];
    *(float4*)&sm[PRE_V + row * 64 + c4 * 4] = *(const float4*)&V[row * DHH + c4 * 4];
  }
  if (tid < 64) sm[PRE_B + tid] = B[tid];
  for (int i = tid; i < 64*65; i += 256) sm[PRE_TI + i] = 0.f;
  __syncthreads();

  {
    const int ty = tid >> 4, tx = tid & 15;
    const int r0 = ty * 4, c0 = tx * 4;
    unsigned long long accA[4][2], accM[4][2];
    #pragma unroll
    for (int m = 0; m < 4; m++){ accA[m][0]=accA[m][1]=accM[m][0]=accM[m][1]=0ull; }
    #pragma unroll 8
    for (int d = 0; d < 64; d++){
      ulonglong2 kc = *(const ulonglong2*)&sm[PRE_KT + d * 68 + c0];
      #pragma unroll
      for (int m = 0; m < 4; m++){
        unsigned long long kr = dup2(sm[PRE_K + (r0+m)*64 + d]);
        unsigned long long qr = dup2(sm[PRE_Q + (r0+m)*64 + d]);
        ffma2(accA[m][0], kr, kc.x);  ffma2(accA[m][1], kr, kc.y);
        ffma2(accM[m][0], qr, kc.x);  ffma2(accM[m][1], qr, kc.y);
      }
    }
    float* Mout = gM + (size_t)cid * (CC*CC);
    #pragma unroll
    for (int m = 0; m < 4; m++){
      const int t = r0 + m;
      const float bt = sm[PRE_B + t];
      float2 a01 = unpk2(accA[m][0]), a23 = unpk2(accA[m][1]);
      float2 m01 = unpk2(accM[m][0]), m23 = unpk2(accM[m][1]);
      float av[4] = {a01.x, a01.y, a23.x, a23.y};
      float mv[4] = {m01.x, m01.y, m23.x, m23.y};
      #pragma unroll
      for (int i = 0; i < 4; i++){
        const int s = c0 + i;
        sm[PRE_A + t*64 + s] = (s < t) ? bt * av[i] : 0.f;
        Mout[t*64 + s]       = (s <= t) ? mv[i] : 0.f;
      }
    }
  }
  __syncthreads();

  if (tid < 64){
    const int c = tid;
    sm[PRE_TI + c*65 + c] = 1.f;
    for (int t = c + 1; t < 64; t++){
      float acc = 0.f;
      for (int j = c; j < t; j++)
        acc += sm[PRE_A + t*64 + j] * sm[PRE_TI + j*65 + c];
      sm[PRE_TI + t*65 + c] = -acc;
    }
  }
  __syncthreads();

  {
    const int ty = tid >> 4, tx = tid & 15;
    const int r0 = ty * 4, c0 = tx * 4;
    unsigned long long accW[4][2], accU[4][2];
    #pragma unroll
    for (int m = 0; m < 4; m++){ accW[m][0]=accW[m][1]=accU[m][0]=accU[m][1]=0ull; }
    #pragma unroll 8
    for (int j = 0; j < 64; j++){
      const float bj = sm[PRE_B + j];
      ulonglong2 k2 = *(const ulonglong2*)&sm[PRE_K + j*64 + c0];
      ulonglong2 v2 = *(const ulonglong2*)&sm[PRE_V + j*64 + c0];
      #pragma unroll
      for (int m = 0; m < 4; m++){
        unsigned long long tb = dup2(sm[PRE_TI + (r0+m)*65 + j] * bj);
        ffma2(accW[m][0], tb, k2.x);  ffma2(accW[m][1], tb, k2.y);
        ffma2(accU[m][0], tb, v2.x);  ffma2(accU[m][1], tb, v2.y);
      }
    }
    float* Wout = gW  + (size_t)cid * (CC*DHH);
    float* Uout = gU0 + (size_t)cid * (CC*DHH);
    #pragma unroll
    for (int m = 0; m < 4; m++){
      const int t = r0 + m;
      float2 w01 = unpk2(accW[m][0]), w23 = unpk2(accW[m][1]);
      float2 u01 = unpk2(accU[m][0]), u23 = unpk2(accU[m][1]);
      *(float4*)&Wout[t*64 + c0] = make_float4(w01.x, w01.y, w23.x, w23.y);
      *(float4*)&Uout[t*64 + c0] = make_float4(u01.x, u01.y, u23.x, u23.y);
    }
  }
}

// ---------------------------------------------------------------------------
// WY sequential pass (unchanged from R5)
// ---------------------------------------------------------------------------
#define SP 20

__global__ __launch_bounds__(256, 1)
void wy_seq(const float* __restrict__ gq, const float* __restrict__ gk,
            const float* __restrict__ gW, const float* __restrict__ gU0,
            const float* __restrict__ gM, float* __restrict__ go)
{
  const int vsplit = blockIdx.x;
  const int bh     = blockIdx.y;
  const int colb   = vsplit * 16;
  const int tid    = threadIdx.x;
  const int trow   = tid >> 2;
  const int vg     = tid & 3;
  const int vo     = vg * 4;

  __shared__ __align__(16) float sS[64 * SP];
  __shared__ __align__(16) float sU[64 * SP];

  for (int i = tid; i < 64 * SP; i += 256) sS[i] = 0.f;
  __syncthreads();

  for (int c = 0; c < NC; c++){
    const size_t cid = (size_t)bh * NC + c;
    const float* Wp  = gW  + cid * (CC*DHH);
    const float* U0p = gU0 + cid * (CC*DHH);
    const float* Mp  = gM  + cid * (CC*CC);
    const float* Kp  = gk + ((size_t)bh * TT + c * CC) * DHH;
    const float* Qp  = gq + ((size_t)bh * TT + c * CC) * DHH;
    float*       Op  = go + ((size_t)bh * TT + c * CC) * DHH + colb;

    {
      float4 u0 = *(const float4*)&U0p[trow*64 + colb + vo];
      unsigned long long a0, a1;
      { unsigned lo0=__float_as_uint(u0.x), hi0=__float_as_uint(u0.y);
        unsigned lo1=__float_as_uint(u0.z), hi1=__float_as_uint(u0.w);
        asm("mov.b64 %0, {%1, %2};" : "=l"(a0) : "r"(lo0), "r"(hi0));
        asm("mov.b64 %0, {%1, %2};" : "=l"(a1) : "r"(lo1), "r"(hi1)); }
      #pragma unroll 8
      for (int kk = 0; kk < 64; kk++){
        unsigned long long nw = dup2(-Wp[trow*64 + kk]);
        ulonglong2 s2 = *(const ulonglong2*)&sS[kk*SP + vo];
        ffma2(a0, nw, s2.x);  ffma2(a1, nw, s2.y);
      }
      *(ulonglong2*)&sU[trow*SP + vo] = make_ulonglong2(a0, a1);
    }
    __syncthreads();

    {
      unsigned long long a0 = 0ull, a1 = 0ull;
      #pragma unroll 8
      for (int j = 0; j < 64; j++){
        unsigned long long qd = dup2(Qp[trow*64 + j]);
        ulonglong2 s2 = *(const ulonglong2*)&sS[j*SP + vo];
        ffma2(a0, qd, s2.x);  ffma2(a1, qd, s2.y);
      }
      #pragma unroll 8
      for (int s = 0; s < 64; s++){
        unsigned long long md = dup2(Mp[trow*64 + s]);
        ulonglong2 u2 = *(const ulonglong2*)&sU[s*SP + vo];
        ffma2(a0, md, u2.x);  ffma2(a1, md, u2.y);
      }
      float2 o01 = unpk2(a0), o23 = unpk2(a1);
      *(float4*)&Op[trow*64 + vo] = make_float4(o01.x, o01.y, o23.x, o23.y);
    }
    __syncthreads();

    {
      ulonglong2 sacc = *(const ulonglong2*)&sS[trow*SP + vo];
      unsigned long long a0 = sacc.x, a1 = sacc.y;
      #pragma unroll 8
      for (int t = 0; t < 64; t++){
        unsigned long long kd = dup2(Kp[t*64 + trow]);
        ulonglong2 u2 = *(const ulonglong2*)&sU[t*SP + vo];
        ffma2(a0, kd, u2.x);  ffma2(a1, kd, u2.y);
      }
      *(ulonglong2*)&sS[trow*SP + vo] = make_ulonglong2(a0, a1);
    }
    __syncthreads();
  }
}

// ---------------------------------------------------------------------------
// Per-head RMSNorm * rms_g, transpose [B,H,T,DH] -> [M,D], fp16 out
// ---------------------------------------------------------------------------
__global__ void rmsnorm_kernel(const float* __restrict__ O, const float* __restrict__ g,
                               __half* __restrict__ YH)
{
  const int m = blockIdx.x;
  const int b = m >> 11, t = m & (TT-1);
  const int tid = threadIdx.x;
  const int h = tid >> 4;
  const int dh0 = (tid & 15) * 4;

  float4 ov = *(const float4*)&O[(((size_t)(b * HH + h)) * TT + t) * DHH + dh0];
  float ss = ov.x*ov.x + ov.y*ov.y + ov.z*ov.z + ov.w*ov.w;
  #pragma unroll
  for (int off = 8; off > 0; off >>= 1)
    ss += __shfl_xor_sync(0xffffffffu, ss, off, 16);
  float sc = rsqrtf(ss * (1.f / 64.f) + 1e-6f);
  float4 gv = *(const float4*)&g[dh0];
  size_t base = (size_t)m * DD + tid * 4;
  *(__half2*)(YH + base)     = __floats2half2_rn(ov.x * sc * gv.x, ov.y * sc * gv.y);
  *(__half2*)(YH + base + 2) = __floats2half2_rn(ov.z * sc * gv.z, ov.w * sc * gv.w);
}

// ---------------------------------------------------------------------------
// Launch
// ---------------------------------------------------------------------------
extern "C" void kernel_launch(void* const* d_in, const int* in_sizes, int n_in,
                              void* d_out, int out_size)
{
  (void)in_sizes; (void)n_in; (void)out_size;
  const float* x  = (const float*)d_in[0];
  const float* Wq = (const float*)d_in[1];
  const float* Wk = (const float*)d_in[2];
  const float* Wv = (const float*)d_in[3];
  const float* Wb = (const float*)d_in[4];
  const float* cq = (const float*)d_in[5];
  const float* ck = (const float*)d_in[6];
  const float* cv = (const float*)d_in[7];
  const float* rg = (const float*)d_in[8];
  const float* Wo = (const float*)d_in[9];
  float* out = (float*)d_out;

  float *qc, *kc, *vc, *q, *k, *v, *beta, *o, *gW, *gU0, *gM;
  __half *xh, *oh, *wt;
  cudaGetSymbolAddress((void**)&qc,  g_qc);
  cudaGetSymbolAddress((void**)&kc,  g_kc);
  cudaGetSymbolAddress((void**)&vc,  g_vc);
  cudaGetSymbolAddress((void**)&q,   g_q);
  cudaGetSymbolAddress((void**)&k,   g_k);
  cudaGetSymbolAddress((void**)&v,   g_v);
  cudaGetSymbolAddress((void**)&beta, g_beta);
  cudaGetSymbolAddress((void**)&o,   g_o);
  cudaGetSymbolAddress((void**)&gW,  g_W);
  cudaGetSymbolAddress((void**)&gU0, g_U0);
  cudaGetSymbolAddress((void**)&gM,  g_M);
  cudaGetSymbolAddress((void**)&xh,  g_xh);
  cudaGetSymbolAddress((void**)&oh,  g_oh);
  cudaGetSymbolAddress((void**)&wt,  g_wt);

  cudaFuncSetAttribute(gemm_mma, cudaFuncAttributeMaxDynamicSharedMemorySize, GEMM_SMEM);
  cudaFuncSetAttribute(wy_pre,   cudaFuncAttributeMaxDynamicSharedMemorySize, PRE_TOT * 4);

  const size_t WSZ = (size_t)DD * DD;
  dim3 wgrid(32, 32), wblk(32, 8);
  dim3 ggrid(DD / 128, MM / 128);

  tohalf_kernel<<<MM * DD / 1024, 256>>>(x, xh);
  wt_kernel<<<wgrid, wblk>>>(Wq, wt + 0*WSZ);
  wt_kernel<<<wgrid, wblk>>>(Wk, wt + 1*WSZ);
  wt_kernel<<<wgrid, wblk>>>(Wv, wt + 2*WSZ);
  wt_kernel<<<wgrid, wblk>>>(Wo, wt + 3*WSZ);

  gemm_mma<<<ggrid, 256, GEMM_SMEM>>>(xh, wt + 0*WSZ, qc);
  gemm_mma<<<ggrid, 256, GEMM_SMEM>>>(xh, wt + 1*WSZ, kc);
  gemm_mma<<<ggrid, 256, GEMM_SMEM>>>(xh, wt + 2*WSZ, vc);

  beta_kernel<<<MM, 64>>>(x, Wb, beta);
  conv_kernel<true ><<<MM, 256>>>(qc, cq, q);
  conv_kernel<true ><<<MM, 256>>>(kc, ck, k);
  conv_kernel<false><<<MM, 256>>>(vc, cv, v);

  wy_pre<<<dim3(NC, NBH), 256, PRE_TOT * 4>>>(q, k, v, beta, gW, gU0, gM);
  wy_seq<<<dim3(4, NBH), 256>>>(q, k, gW, gU0, gM, o);

  rmsnorm_kernel<<<MM, 256>>>(o, rg, oh);
  gemm_mma<<<ggrid, 256, GEMM_SMEM>>>(oh, wt + 3*WSZ, out);
}

// round 9
// speedup vs baseline: 2.1607x; 1.0622x over previous
#include <cuda_runtime.h>
#include <cuda_fp16.h>
#include <cstdint>

// Problem constants
#define BB 2
#define TT 2048
#define DD 1024
#define HH 16
#define DHH 64
#define MM (BB*TT)          // 4096 rows
#define CC 64               // WY chunk length
#define NC (TT/CC)          // 32 chunks per (b,h)
#define NBH (BB*HH)         // 32
#define NCHT (NBH*NC)       // 1024 chunk-heads

// ---------------------------------------------------------------------------
// Scratch (device globals: no runtime allocation allowed)
// ---------------------------------------------------------------------------
__device__ float g_qc[MM*DD];
__device__ float g_kc[MM*DD];
__device__ float g_vc[MM*DD];
__device__ float g_q [MM*DD];
__device__ float g_k [MM*DD];
__device__ float g_v [MM*DD];
__device__ float g_beta[BB*HH*TT];
__device__ float g_o [MM*DD];

__device__ float g_W [NCHT*CC*DHH];
__device__ float g_U0[NCHT*CC*DHH];
__device__ float g_M [NCHT*CC*CC];

__device__ __half g_xh[MM*DD];
__device__ __half g_oh[MM*DD];
__device__ __half g_wt[4][DD*DD];      // W^T fp16 [N,K] for Wq,Wk,Wv,Wo (contiguous)

// ---------------------------------------------------------------------------
// f32x2 packed helpers
// ---------------------------------------------------------------------------
__device__ __forceinline__ unsigned long long dup2(float x){
  unsigned long long r;
  unsigned u = __float_as_uint(x);
  asm("mov.b64 %0, {%1, %1};" : "=l"(r) : "r"(u));
  return r;
}
__device__ __forceinline__ void ffma2(unsigned long long &c, unsigned long long a, unsigned long long b){
  asm("fma.rn.f32x2 %0, %1, %2, %0;" : "+l"(c) : "l"(a), "l"(b));
}
__device__ __forceinline__ float2 unpk2(unsigned long long p){
  unsigned lo, hi;
  asm("mov.b64 {%0, %1}, %2;" : "=r"(lo), "=r"(hi) : "l"(p));
  return make_float2(__uint_as_float(lo), __uint_as_float(hi));
}

// ---------------------------------------------------------------------------
// smem / cp.async / mma helpers
// ---------------------------------------------------------------------------
__device__ __forceinline__ uint32_t smem_u32(const void* p){
  uint32_t a;
  asm("{ .reg .u64 t; cvta.to.shared.u64 t, %1; cvt.u32.u64 %0, t; }" : "=r"(a) : "l"(p));
  return a;
}
__device__ __forceinline__ void cpasync16(uint32_t dst, const void* src){
  asm volatile("cp.async.cg.shared.global [%0], [%1], 16;" :: "r"(dst), "l"(src));
}
__device__ __forceinline__ void cpasync_commit(){
  asm volatile("cp.async.commit_group;" ::: "memory");
}
__device__ __forceinline__ void ldm4(uint32_t* r, uint32_t addr){
  asm volatile("ldmatrix.sync.aligned.m8n8.x4.shared.b16 {%0,%1,%2,%3}, [%4];"
               : "=r"(r[0]), "=r"(r[1]), "=r"(r[2]), "=r"(r[3]) : "r"(addr));
}
__device__ __forceinline__ void mma16816h(float* d, const uint32_t* a, const uint32_t* b){
  asm volatile(
    "mma.sync.aligned.m16n8k16.row.col.f32.f16.f16.f32 "
    "{%0,%1,%2,%3}, {%4,%5,%6,%7}, {%8,%9}, {%0,%1,%2,%3};"
    : "+f"(d[0]), "+f"(d[1]), "+f"(d[2]), "+f"(d[3])
    : "r"(a[0]), "r"(a[1]), "r"(a[2]), "r"(a[3]), "r"(b[0]), "r"(b[1]));
}

// ---------------------------------------------------------------------------
// fp16 GEMM, 4-stage cp.async, smem-staged coalesced epilogue.
// Grid.x encodes (proj, tileN): proj = bx>>3 selects B plane + C buffer.
// Tile 128x128, K-chunk 32, 8 warps = 2(M) x 4(N).
// ---------------------------------------------------------------------------
#define GK   1024
#define KC   32
#define NCHG (GK/KC)           // 32
#define ROWB 80
#define MATB (128*ROWB)        // 10240
#define STAGEB (2*MATB)        // 20480
#define NSTAGE 4
#define GEMM_SMEM (NSTAGE*STAGEB)   // 81920  (epilogue staging reuses this)
#define EPI_PITCH 132

__global__ __launch_bounds__(256, 2)
void gemm_mma(const __half* __restrict__ A, const __half* __restrict__ Bbase,
              float* __restrict__ C0, float* __restrict__ C1, float* __restrict__ C2)
{
  extern __shared__ char smem[];
  const uint32_t sb = smem_u32(smem);
  const int tid   = threadIdx.x;
  const int wid   = tid >> 5;
  const int lane  = tid & 31;
  const int warpM = wid & 1;
  const int warpN = wid >> 1;
  const int proj  = blockIdx.x >> 3;
  const int tileN = (blockIdx.x & 7) * 128;
  const int tileM = blockIdx.y * 128;
  const __half* B = Bbase + (size_t)proj * (DD*DD);
  float* Cout = (proj == 0) ? C0 : ((proj == 1) ? C1 : C2);

  const __half* gsrc[2] = { A + (size_t)tileM * GK, B + (size_t)tileN * GK };

  auto load_stage = [&](int s, int kt){
    const uint32_t base = sb + s * STAGEB;
    #pragma unroll
    for (int i = 0; i < 4; i++){
      int cid = tid + i * 256;
      int mat = cid >> 9;
      int rem = cid & 511;
      int row = rem >> 2, ch = rem & 3;
      cpasync16(base + mat * MATB + row * ROWB + ch * 16,
                gsrc[mat] + (size_t)row * GK + kt + ch * 8);
    }
  };

  float acc[4][4][4];
  #pragma unroll
  for (int mt = 0; mt < 4; mt++)
    #pragma unroll
    for (int nt = 0; nt < 4; nt++)
      #pragma unroll
      for (int j = 0; j < 4; j++) acc[mt][nt][j] = 0.f;

  const int aRow   = lane & 15;
  const int aKhalf = lane >> 4;
  const uint32_t aOff = (uint32_t)(warpM*64 + aRow) * ROWB + aKhalf * 16;
  const int bRow   = (lane & 7) + ((lane >> 4) << 3);
  const int bKhalf = (lane >> 3) & 1;
  const uint32_t bOff = (uint32_t)(warpN*32 + bRow) * ROWB + bKhalf * 16;

  load_stage(0, 0);      cpasync_commit();
  load_stage(1, KC);     cpasync_commit();
  load_stage(2, 2*KC);   cpasync_commit();

  for (int c = 0; c < NCHG; c++){
    if (c <= NCHG-3)      asm volatile("cp.async.wait_group 2;" ::: "memory");
    else if (c == NCHG-2) asm volatile("cp.async.wait_group 1;" ::: "memory");
    else                  asm volatile("cp.async.wait_group 0;" ::: "memory");
    __syncthreads();

    if (c + 3 < NCHG){ load_stage((c + 3) & 3, (c + 3) * KC); cpasync_commit(); }

    const uint32_t sbuf = sb + (c & 3) * STAGEB;
    #pragma unroll
    for (int ks = 0; ks < 2; ks++){
      const uint32_t koff = ks * 32;
      uint32_t ar[4][4], br[2][4];
      #pragma unroll
      for (int mt = 0; mt < 4; mt++)
        ldm4(ar[mt], sbuf + 0*MATB + aOff + mt*16*ROWB + koff);
      #pragma unroll
      for (int p = 0; p < 2; p++)
        ldm4(br[p], sbuf + 1*MATB + bOff + p*16*ROWB + koff);
      #pragma unroll
      for (int mt = 0; mt < 4; mt++)
        #pragma unroll
        for (int nt = 0; nt < 4; nt++)
          mma16816h(acc[mt][nt], ar[mt], &br[nt>>1][(nt&1)*2]);
    }
    __syncthreads();
  }

  // ---- staged epilogue: 4 rounds of 32 rows x 128 cols, coalesced stores ----
  float* sOut = (float*)smem;
  const int lrow = lane >> 2;                 // 0..7
  const int lcol = warpN*32 + (lane & 3)*2;
  #pragma unroll
  for (int mt = 0; mt < 4; mt++){
    #pragma unroll
    for (int nt = 0; nt < 4; nt++){
      float* p0 = &sOut[(warpM*16 + lrow    ) * EPI_PITCH + lcol + nt*8];
      float* p1 = &sOut[(warpM*16 + lrow + 8) * EPI_PITCH + lcol + nt*8];
      p0[0] = acc[mt][nt][0]; p0[1] = acc[mt][nt][1];
      p1[0] = acc[mt][nt][2]; p1[1] = acc[mt][nt][3];
    }
    __syncthreads();
    #pragma unroll
    for (int i = 0; i < 4; i++){
      int idx = tid + i * 256;                // 0..1023 float4 units
      int r = idx >> 5, c4 = idx & 31;
      int gr = tileM + (r >> 4) * 64 + mt * 16 + (r & 15);
      float4 val = *(float4*)&sOut[r * EPI_PITCH + c4 * 4];
      *(float4*)&Cout[(size_t)gr * GK + tileN + c4 * 4] = val;
    }
    __syncthreads();
  }
}

// ---------------------------------------------------------------------------
// fp32 -> fp16
// ---------------------------------------------------------------------------
__global__ void tohalf_kernel(const float* __restrict__ X, __half* __restrict__ H)
{
  int i = (blockIdx.x * 256 + threadIdx.x) * 4;
  float4 xv = *(const float4*)(X + i);
  *(__half2*)(H + i)     = __floats2half2_rn(xv.x, xv.y);
  *(__half2*)(H + i + 2) = __floats2half2_rn(xv.z, xv.w);
}

// ---------------------------------------------------------------------------
// Weight transpose + fp16: W[K,N] fp32 -> Wt [N,K] fp16
// ---------------------------------------------------------------------------
__global__ void wt_kernel(const float* __restrict__ W, __half* __restrict__ TH)
{
  __shared__ float tile[32][33];
  const int n0 = blockIdx.x * 32, k0 = blockIdx.y * 32;
  const int tx = threadIdx.x, ty = threadIdx.y;
  #pragma unroll
  for (int i = 0; i < 4; i++)
    tile[ty + i*8][tx] = W[(size_t)(k0 + ty + i*8) * DD + n0 + tx];
  __syncthreads();
  #pragma unroll
  for (int i = 0; i < 4; i++){
    float v = tile[tx][ty + i*8];
    TH[(size_t)(n0 + ty + i*8) * DD + k0 + tx] = __float2half_rn(v);
  }
}

// ---------------------------------------------------------------------------
// beta = sigmoid(x @ Wb)
// ---------------------------------------------------------------------------
__global__ void beta_kernel(const float* __restrict__ x, const float* __restrict__ Wb,
                            float* __restrict__ gb)
{
  const int m = blockIdx.x;
  const int tid = threadIdx.x;
  const int h = tid & 15, part = tid >> 4;
  __shared__ float sx[DD];
  for (int i = tid; i < DD/4; i += 64)
    *(float4*)&sx[i*4] = *(const float4*)&x[(size_t)m * DD + i*4];
  __syncthreads();
  float acc = 0.f;
  const int kbase = part * 256;
  for (int kk = 0; kk < 256; kk++)
    acc += sx[kbase + kk] * Wb[(size_t)(kbase + kk) * HH + h];
  __shared__ float red[64];
  red[tid] = acc;
  __syncthreads();
  if (tid < 16) {
    float s = red[tid] + red[tid+16] + red[tid+32] + red[tid+48];
    int b = m >> 11, t = m & (TT-1);
    gb[((size_t)b * HH + tid) * TT + t] = 1.f / (1.f + __expf(-s));
  }
}

// ---------------------------------------------------------------------------
// Fused 3-way causal depthwise conv (K=4) + SiLU (+ L2 norm for q,k).
// blockIdx.y selects q/k/v stream. [M,D] -> [B,H,T,DH]
// ---------------------------------------------------------------------------
__global__ void conv3_kernel(const float* __restrict__ Xq, const float* __restrict__ Xk,
                             const float* __restrict__ Xv,
                             const float* __restrict__ Wq, const float* __restrict__ Wk,
                             const float* __restrict__ Wv,
                             float* __restrict__ Yq, float* __restrict__ Yk,
                             float* __restrict__ Yv)
{
  const int which = blockIdx.y;
  const float* X = (which == 0) ? Xq : (which == 1) ? Xk : Xv;
  const float* W = (which == 0) ? Wq : (which == 1) ? Wk : Wv;
  float*       Y = (which == 0) ? Yq : (which == 1) ? Yk : Yv;
  const bool norm = (which < 2);

  const int m = blockIdx.x;
  const int b = m >> 11, t = m & (TT-1);
  const int tid = threadIdx.x;
  const int c0 = tid * 4;

  float warr[4][4];
  #pragma unroll
  for (int j = 0; j < 4; j++) {
    float4 wv = *(const float4*)&W[(size_t)(c0 + j) * 4];
    warr[j][0] = wv.x; warr[j][1] = wv.y; warr[j][2] = wv.z; warr[j][3] = wv.w;
  }
  float acc[4] = {0.f, 0.f, 0.f, 0.f};
  #pragma unroll
  for (int i = 0; i < 4; i++) {
    int tt = t - 3 + i;
    if (tt >= 0) {
      float4 xv = *(const float4*)&X[((size_t)(b * TT + tt)) * DD + c0];
      acc[0] += warr[0][i] * xv.x;
      acc[1] += warr[1][i] * xv.y;
      acc[2] += warr[2][i] * xv.z;
      acc[3] += warr[3][i] * xv.w;
    }
  }
  float y[4];
  #pragma unroll
  for (int j = 0; j < 4; j++) {
    float s = 1.f / (1.f + __expf(-acc[j]));
    y[j] = acc[j] * s;
  }
  float scale = 1.f;
  if (norm) {
    float ss = y[0]*y[0] + y[1]*y[1] + y[2]*y[2] + y[3]*y[3];
    #pragma unroll
    for (int off = 8; off > 0; off >>= 1)
      ss += __shfl_xor_sync(0xffffffffu, ss, off, 16);
    scale = rsqrtf(ss + 1e-6f);
  }
  const int h = tid >> 4;
  const int dh0 = (tid & 15) * 4;
  *(float4*)&Y[(((size_t)(b * HH + h)) * TT + t) * DHH + dh0] =
      make_float4(y[0]*scale, y[1]*scale, y[2]*scale, y[3]*scale);
}

// ---------------------------------------------------------------------------
// WY precompute (unchanged)
// ---------------------------------------------------------------------------
#define PRE_K  0
#define PRE_V  4096
#define PRE_Q  8192
#define PRE_KT 12288          // pitch 68
#define PRE_A  16640
#define PRE_TI 20736          // pitch 65
#define PRE_B  24896
#define PRE_TOT 24960

__global__ __launch_bounds__(256, 1)
void wy_pre(const float* __restrict__ gq, const float* __restrict__ gk,
            const float* __restrict__ gv, const float* __restrict__ gb,
            float* __restrict__ gW, float* __restrict__ gU0, float* __restrict__ gM)
{
  extern __shared__ float sm[];
  const int chunk = blockIdx.x;
  const int bh    = blockIdx.y;
  const int cid   = bh * NC + chunk;
  const int tid   = threadIdx.x;

  const float* K = gk + ((size_t)bh * TT + chunk * CC) * DHH;
  const float* Q = gq + ((size_t)bh * TT + chunk * CC) * DHH;
  const float* V = gv + ((size_t)bh * TT + chunk * CC) * DHH;
  const float* B = gb + (size_t)bh * TT + chunk * CC;

  #pragma unroll
  for (int i = 0; i < 4; i++){
    int idx  = tid + i * 256;
    int row  = idx >> 4, c4 = idx & 15;
    float4 kv = *(const float4*)&K[row * DHH + c4 * 4];
    *(float4*)&sm[PRE_K + row * 64 + c4 * 4] = kv;
    sm[PRE_KT + (c4*4+0) * 68 + row] = kv.x;
    sm[PRE_KT + (c4*4+1) * 68 + row] = kv.y;
    sm[PRE_KT + (c4*4+2) * 68 + row] = kv.z;
    sm[PRE_KT + (c4*4+3) * 68 + row] = kv.w;
    *(float4*)&sm[PRE_Q + row * 64 + c4 * 4] = *(const float4*)&Q[row * DHH + c4 * 4];
    *(float4*)&sm[PRE_V + row * 64 + c4 * 4] = *(const float4*)&V[row * DHH + c4 * 4];
  }
  if (tid < 64) sm[PRE_B + tid] = B[tid];
  for (int i = tid; i < 64*65; i += 256) sm[PRE_TI + i] = 0.f;
  __syncthreads();

  {
    const int ty = tid >> 4, tx = tid & 15;
    const int r0 = ty * 4, c0 = tx * 4;
    unsigned long long accA[4][2], accM[4][2];
    #pragma unroll
    for (int m = 0; m < 4; m++){ accA[m][0]=accA[m][1]=accM[m][0]=accM[m][1]=0ull; }
    #pragma unroll 8
    for (int d = 0; d < 64; d++){
      ulonglong2 kc = *(const ulonglong2*)&sm[PRE_KT + d * 68 + c0];
      #pragma unroll
      for (int m = 0; m < 4; m++){
        unsigned long long kr = dup2(sm[PRE_K + (r0+m)*64 + d]);
        unsigned long long qr = dup2(sm[PRE_Q + (r0+m)*64 + d]);
        ffma2(accA[m][0], kr, kc.x);  ffma2(accA[m][1], kr, kc.y);
        ffma2(accM[m][0], qr, kc.x);  ffma2(accM[m][1], qr, kc.y);
      }
    }
    float* Mout = gM + (size_t)cid * (CC*CC);
    #pragma unroll
    for (int m = 0; m < 4; m++){
      const int t = r0 + m;
      const float bt = sm[PRE_B + t];
      float2 a01 = unpk2(accA[m][0]), a23 = unpk2(accA[m][1]);
      float2 m01 = unpk2(accM[m][0]), m23 = unpk2(accM[m][1]);
      float av[4] = {a01.x, a01.y, a23.x, a23.y};
      float mv[4] = {m01.x, m01.y, m23.x, m23.y};
      #pragma unroll
      for (int i = 0; i < 4; i++){
        const int s = c0 + i;
        sm[PRE_A + t*64 + s] = (s < t) ? bt * av[i] : 0.f;
        Mout[t*64 + s]       = (s <= t) ? mv[i] : 0.f;
      }
    }
  }
  __syncthreads();

  if (tid < 64){
    const int c = tid;
    sm[PRE_TI + c*65 + c] = 1.f;
    for (int t = c + 1; t < 64; t++){
      float acc = 0.f;
      for (int j = c; j < t; j++)
        acc += sm[PRE_A + t*64 + j] * sm[PRE_TI + j*65 + c];
      sm[PRE_TI + t*65 + c] = -acc;
    }
  }
  __syncthreads();

  {
    const int ty = tid >> 4, tx = tid & 15;
    const int r0 = ty * 4, c0 = tx * 4;
    unsigned long long accW[4][2], accU[4][2];
    #pragma unroll
    for (int m = 0; m < 4; m++){ accW[m][0]=accW[m][1]=accU[m][0]=accU[m][1]=0ull; }
    #pragma unroll 8
    for (int j = 0; j < 64; j++){
      const float bj = sm[PRE_B + j];
      ulonglong2 k2 = *(const ulonglong2*)&sm[PRE_K + j*64 + c0];
      ulonglong2 v2 = *(const ulonglong2*)&sm[PRE_V + j*64 + c0];
      #pragma unroll
      for (int m = 0; m < 4; m++){
        unsigned long long tb = dup2(sm[PRE_TI + (r0+m)*65 + j] * bj);
        ffma2(accW[m][0], tb, k2.x);  ffma2(accW[m][1], tb, k2.y);
        ffma2(accU[m][0], tb, v2.x);  ffma2(accU[m][1], tb, v2.y);
      }
    }
    float* Wout = gW  + (size_t)cid * (CC*DHH);
    float* Uout = gU0 + (size_t)cid * (CC*DHH);
    #pragma unroll
    for (int m = 0; m < 4; m++){
      const int t = r0 + m;
      float2 w01 = unpk2(accW[m][0]), w23 = unpk2(accW[m][1]);
      float2 u01 = unpk2(accU[m][0]), u23 = unpk2(accU[m][1]);
      *(float4*)&Wout[t*64 + c0] = make_float4(w01.x, w01.y, w23.x, w23.y);
      *(float4*)&Uout[t*64 + c0] = make_float4(u01.x, u01.y, u23.x, u23.y);
    }
  }
}

// ---------------------------------------------------------------------------
// WY sequential pass (unchanged)
// ---------------------------------------------------------------------------
#define SP 20

__global__ __launch_bounds__(256, 1)
void wy_seq(const float* __restrict__ gq, const float* __restrict__ gk,
            const float* __restrict__ gW, const float* __restrict__ gU0,
            const float* __restrict__ gM, float* __restrict__ go)
{
  const int vsplit = blockIdx.x;
  const int bh     = blockIdx.y;
  const int colb   = vsplit * 16;
  const int tid    = threadIdx.x;
  const int trow   = tid >> 2;
  const int vg     = tid & 3;
  const int vo     = vg * 4;

  __shared__ __align__(16) float sS[64 * SP];
  __shared__ __align__(16) float sU[64 * SP];

  for (int i = tid; i < 64 * SP; i += 256) sS[i] = 0.f;
  __syncthreads();

  for (int c = 0; c < NC; c++){
    const size_t cid = (size_t)bh * NC + c;
    const float* Wp  = gW  + cid * (CC*DHH);
    const float* U0p = gU0 + cid * (CC*DHH);
    const float* Mp  = gM  + cid * (CC*CC);
    const float* Kp  = gk + ((size_t)bh * TT + c * CC) * DHH;
    const float* Qp  = gq + ((size_t)bh * TT + c * CC) * DHH;
    float*       Op  = go + ((size_t)bh * TT + c * CC) * DHH + colb;

    {
      float4 u0 = *(const float4*)&U0p[trow*64 + colb + vo];
      unsigned long long a0, a1;
      { unsigned lo0=__float_as_uint(u0.x), hi0=__float_as_uint(u0.y);
        unsigned lo1=__float_as_uint(u0.z), hi1=__float_as_uint(u0.w);
        asm("mov.b64 %0, {%1, %2};" : "=l"(a0) : "r"(lo0), "r"(hi0));
        asm("mov.b64 %0, {%1, %2};" : "=l"(a1) : "r"(lo1), "r"(hi1)); }
      #pragma unroll 8
      for (int kk = 0; kk < 64; kk++){
        unsigned long long nw = dup2(-Wp[trow*64 + kk]);
        ulonglong2 s2 = *(const ulonglong2*)&sS[kk*SP + vo];
        ffma2(a0, nw, s2.x);  ffma2(a1, nw, s2.y);
      }
      *(ulonglong2*)&sU[trow*SP + vo] = make_ulonglong2(a0, a1);
    }
    __syncthreads();

    {
      unsigned long long a0 = 0ull, a1 = 0ull;
      #pragma unroll 8
      for (int j = 0; j < 64; j++){
        unsigned long long qd = dup2(Qp[trow*64 + j]);
        ulonglong2 s2 = *(const ulonglong2*)&sS[j*SP + vo];
        ffma2(a0, qd, s2.x);  ffma2(a1, qd, s2.y);
      }
      #pragma unroll 8
      for (int s = 0; s < 64; s++){
        unsigned long long md = dup2(Mp[trow*64 + s]);
        ulonglong2 u2 = *(const ulonglong2*)&sU[s*SP + vo];
        ffma2(a0, md, u2.x);  ffma2(a1, md, u2.y);
      }
      float2 o01 = unpk2(a0), o23 = unpk2(a1);
      *(float4*)&Op[trow*64 + vo] = make_float4(o01.x, o01.y, o23.x, o23.y);
    }
    __syncthreads();

    {
      ulonglong2 sacc = *(const ulonglong2*)&sS[trow*SP + vo];
      unsigned long long a0 = sacc.x, a1 = sacc.y;
      #pragma unroll 8
      for (int t = 0; t < 64; t++){
        unsigned long long kd = dup2(Kp[t*64 + trow]);
        ulonglong2 u2 = *(const ulonglong2*)&sU[t*SP + vo];
        ffma2(a0, kd, u2.x);  ffma2(a1, kd, u2.y);
      }
      *(ulonglong2*)&sS[trow*SP + vo] = make_ulonglong2(a0, a1);
    }
    __syncthreads();
  }
}

// ---------------------------------------------------------------------------
// Per-head RMSNorm * rms_g, transpose -> [M,D], fp16 out
// ---------------------------------------------------------------------------
__global__ void rmsnorm_kernel(const float* __restrict__ O, const float* __restrict__ g,
                               __half* __restrict__ YH)
{
  const int m = blockIdx.x;
  const int b = m >> 11, t = m & (TT-1);
  const int tid = threadIdx.x;
  const int h = tid >> 4;
  const int dh0 = (tid & 15) * 4;

  float4 ov = *(const float4*)&O[(((size_t)(b * HH + h)) * TT + t) * DHH + dh0];
  float ss = ov.x*ov.x + ov.y*ov.y + ov.z*ov.z + ov.w*ov.w;
  #pragma unroll
  for (int off = 8; off > 0; off >>= 1)
    ss += __shfl_xor_sync(0xffffffffu, ss, off, 16);
  float sc = rsqrtf(ss * (1.f / 64.f) + 1e-6f);
  float4 gv = *(const float4*)&g[dh0];
  size_t base = (size_t)m * DD + tid * 4;
  *(__half2*)(YH + base)     = __floats2half2_rn(ov.x * sc * gv.x, ov.y * sc * gv.y);
  *(__half2*)(YH + base + 2) = __floats2half2_rn(ov.z * sc * gv.z, ov.w * sc * gv.w);
}

// ---------------------------------------------------------------------------
// Launch
// ---------------------------------------------------------------------------
extern "C" void kernel_launch(void* const* d_in, const int* in_sizes, int n_in,
                              void* d_out, int out_size)
{
  (void)in_sizes; (void)n_in; (void)out_size;
  const float* x  = (const float*)d_in[0];
  const float* Wq = (const float*)d_in[1];
  const float* Wk = (const float*)d_in[2];
  const float* Wv = (const float*)d_in[3];
  const float* Wb = (const float*)d_in[4];
  const float* cq = (const float*)d_in[5];
  const float* ck = (const float*)d_in[6];
  const float* cv = (const float*)d_in[7];
  const float* rg = (const float*)d_in[8];
  const float* Wo = (const float*)d_in[9];
  float* out = (float*)d_out;

  float *qc, *kc, *vc, *q, *k, *v, *beta, *o, *gW, *gU0, *gM;
  __half *xh, *oh, *wt;
  cudaGetSymbolAddress((void**)&qc,  g_qc);
  cudaGetSymbolAddress((void**)&kc,  g_kc);
  cudaGetSymbolAddress((void**)&vc,  g_vc);
  cudaGetSymbolAddress((void**)&q,   g_q);
  cudaGetSymbolAddress((void**)&k,   g_k);
  cudaGetSymbolAddress((void**)&v,   g_v);
  cudaGetSymbolAddress((void**)&beta, g_beta);
  cudaGetSymbolAddress((void**)&o,   g_o);
  cudaGetSymbolAddress((void**)&gW,  g_W);
  cudaGetSymbolAddress((void**)&gU0, g_U0);
  cudaGetSymbolAddress((void**)&gM,  g_M);
  cudaGetSymbolAddress((void**)&xh,  g_xh);
  cudaGetSymbolAddress((void**)&oh,  g_oh);
  cudaGetSymbolAddress((void**)&wt,  g_wt);

  cudaFuncSetAttribute(gemm_mma, cudaFuncAttributeMaxDynamicSharedMemorySize, GEMM_SMEM);
  cudaFuncSetAttribute(wy_pre,   cudaFuncAttributeMaxDynamicSharedMemorySize, PRE_TOT * 4);

  const size_t WSZ = (size_t)DD * DD;
  dim3 wgrid(32, 32), wblk(32, 8);

  tohalf_kernel<<<MM * DD / 1024, 256>>>(x, xh);
  wt_kernel<<<wgrid, wblk>>>(Wq, wt + 0*WSZ);
  wt_kernel<<<wgrid, wblk>>>(Wk, wt + 1*WSZ);
  wt_kernel<<<wgrid, wblk>>>(Wv, wt + 2*WSZ);
  wt_kernel<<<wgrid, wblk>>>(Wo, wt + 3*WSZ);

  // fused QKV projection: 768 CTAs, proj = blockIdx.x>>3
  gemm_mma<<<dim3(24, MM/128), 256, GEMM_SMEM>>>(xh, wt, qc, kc, vc);

  beta_kernel<<<MM, 64>>>(x, Wb, beta);
  conv3_kernel<<<dim3(MM, 3), 256>>>(qc, kc, vc, cq, ck, cv, q, k, v);

  wy_pre<<<dim3(NC, NBH), 256, PRE_TOT * 4>>>(q, k, v, beta, gW, gU0, gM);
  wy_seq<<<dim3(4, NBH), 256>>>(q, k, gW, gU0, gM, o);

  rmsnorm_kernel<<<MM, 256>>>(o, rg, oh);
  // output projection: grid.x = 8 -> proj = 0, B = wt+3*WSZ
  gemm_mma<<<dim3(8, MM/128), 256, GEMM_SMEM>>>(oh, wt + 3*WSZ, out, out, out);
}

// round 11
// speedup vs baseline: 3.3736x; 1.5614x over previous
#include <cuda_runtime.h>
#include <cuda_fp16.h>
#include <cstdint>

// Problem constants
#define BB 2
#define TT 2048
#define DD 1024
#define HH 16
#define DHH 64
#define MM (BB*TT)
#define CC 64
#define NC (TT/CC)
#define NBH (BB*HH)
#define NCHT (NBH*NC)

// ---------------------------------------------------------------------------
// Scratch
// ---------------------------------------------------------------------------
__device__ __half g_qch[MM*DD];   // fp16 pre-conv projections
__device__ __half g_kch[MM*DD];
__device__ __half g_vch[MM*DD];
__device__ float g_q [MM*DD];
__device__ float g_k [MM*DD];
__device__ float g_v [MM*DD];
__device__ float g_beta[BB*HH*TT];
__device__ float g_o [MM*DD];

__device__ float g_W [NCHT*CC*DHH];
__device__ float g_U0[NCHT*CC*DHH];
__device__ float g_M [NCHT*CC*CC];

__device__ __half g_xh[MM*DD];
__device__ __half g_oh[MM*DD];
__device__ __half g_wt[4][DD*DD];

// ---------------------------------------------------------------------------
// f32x2 helpers
// ---------------------------------------------------------------------------
__device__ __forceinline__ unsigned long long dup2(float x){
  unsigned long long r;
  unsigned u = __float_as_uint(x);
  asm("mov.b64 %0, {%1, %1};" : "=l"(r) : "r"(u));
  return r;
}
__device__ __forceinline__ void ffma2(unsigned long long &c, unsigned long long a, unsigned long long b){
  asm("fma.rn.f32x2 %0, %1, %2, %0;" : "+l"(c) : "l"(a), "l"(b));
}
__device__ __forceinline__ float2 unpk2(unsigned long long p){
  unsigned lo, hi;
  asm("mov.b64 {%0, %1}, %2;" : "=r"(lo), "=r"(hi) : "l"(p));
  return make_float2(__uint_as_float(lo), __uint_as_float(hi));
}

// ---------------------------------------------------------------------------
// smem / cp.async / mma helpers
// ---------------------------------------------------------------------------
__device__ __forceinline__ uint32_t smem_u32(const void* p){
  uint32_t a;
  asm("{ .reg .u64 t; cvta.to.shared.u64 t, %1; cvt.u32.u64 %0, t; }" : "=r"(a) : "l"(p));
  return a;
}
__device__ __forceinline__ void cpasync16(uint32_t dst, const void* src){
  asm volatile("cp.async.cg.shared.global [%0], [%1], 16;" :: "r"(dst), "l"(src));
}
__device__ __forceinline__ void cpasync_commit(){
  asm volatile("cp.async.commit_group;" ::: "memory");
}
__device__ __forceinline__ void ldm4(uint32_t* r, uint32_t addr){
  asm volatile("ldmatrix.sync.aligned.m8n8.x4.shared.b16 {%0,%1,%2,%3}, [%4];"
               : "=r"(r[0]), "=r"(r[1]), "=r"(r[2]), "=r"(r[3]) : "r"(addr));
}
__device__ __forceinline__ void mma16816h(float* d, const uint32_t* a, const uint32_t* b){
  asm volatile(
    "mma.sync.aligned.m16n8k16.row.col.f32.f16.f16.f32 "
    "{%0,%1,%2,%3}, {%4,%5,%6,%7}, {%8,%9}, {%0,%1,%2,%3};"
    : "+f"(d[0]), "+f"(d[1]), "+f"(d[2]), "+f"(d[3])
    : "r"(a[0]), "r"(a[1]), "r"(a[2]), "r"(a[3]), "r"(b[0]), "r"(b[1]));
}

// ---------------------------------------------------------------------------
// fp16 GEMM, 4-stage cp.async, one sync per chunk, staged epilogue.
// CT = float or __half output.
// ---------------------------------------------------------------------------
#define GK   1024
#define KC   32
#define NCHG (GK/KC)
#define ROWB 80
#define MATB (128*ROWB)
#define STAGEB (2*MATB)
#define NSTAGE 4
#define GEMM_SMEM (NSTAGE*STAGEB)
#define EPI_PITCH 132

template<typename CT>
__global__ __launch_bounds__(256, 2)
void gemm_mma(const __half* __restrict__ A, const __half* __restrict__ Bbase,
              CT* __restrict__ C0, CT* __restrict__ C1, CT* __restrict__ C2)
{
  extern __shared__ char smem[];
  const uint32_t sb = smem_u32(smem);
  const int tid   = threadIdx.x;
  const int wid   = tid >> 5;
  const int lane  = tid & 31;
  const int warpM = wid & 1;
  const int warpN = wid >> 1;
  const int proj  = blockIdx.x >> 3;
  const int tileN = (blockIdx.x & 7) * 128;
  const int tileM = blockIdx.y * 128;
  const __half* B = Bbase + (size_t)proj * (DD*DD);
  CT* Cout = (proj == 0) ? C0 : ((proj == 1) ? C1 : C2);

  const __half* gsrc[2] = { A + (size_t)tileM * GK, B + (size_t)tileN * GK };

  auto load_stage = [&](int s, int kt){
    const uint32_t base = sb + s * STAGEB;
    #pragma unroll
    for (int i = 0; i < 4; i++){
      int cid = tid + i * 256;
      int mat = cid >> 9;
      int rem = cid & 511;
      int row = rem >> 2, ch = rem & 3;
      cpasync16(base + mat * MATB + row * ROWB + ch * 16,
                gsrc[mat] + (size_t)row * GK + kt + ch * 8);
    }
  };

  float acc[4][4][4];
  #pragma unroll
  for (int mt = 0; mt < 4; mt++)
    #pragma unroll
    for (int nt = 0; nt < 4; nt++)
      #pragma unroll
      for (int j = 0; j < 4; j++) acc[mt][nt][j] = 0.f;

  const int aRow   = lane & 15;
  const int aKhalf = lane >> 4;
  const uint32_t aOff = (uint32_t)(warpM*64 + aRow) * ROWB + aKhalf * 16;
  const int bRow   = (lane & 7) + ((lane >> 4) << 3);
  const int bKhalf = (lane >> 3) & 1;
  const uint32_t bOff = (uint32_t)(warpN*32 + bRow) * ROWB + bKhalf * 16;

  load_stage(0, 0);      cpasync_commit();
  load_stage(1, KC);     cpasync_commit();
  load_stage(2, 2*KC);   cpasync_commit();

  for (int c = 0; c < NCHG; c++){
    if (c <= NCHG-3)      asm volatile("cp.async.wait_group 2;" ::: "memory");
    else if (c == NCHG-2) asm volatile("cp.async.wait_group 1;" ::: "memory");
    else                  asm volatile("cp.async.wait_group 0;" ::: "memory");
    __syncthreads();

    if (c + 3 < NCHG){ load_stage((c + 3) & 3, (c + 3) * KC); cpasync_commit(); }

    const uint32_t sbuf = sb + (c & 3) * STAGEB;
    #pragma unroll
    for (int ks = 0; ks < 2; ks++){
      const uint32_t koff = ks * 32;
      uint32_t ar[4][4], br[2][4];
      #pragma unroll
      for (int mt = 0; mt < 4; mt++)
        ldm4(ar[mt], sbuf + 0*MATB + aOff + mt*16*ROWB + koff);
      #pragma unroll
      for (int p = 0; p < 2; p++)
        ldm4(br[p], sbuf + 1*MATB + bOff + p*16*ROWB + koff);
      #pragma unroll
      for (int mt = 0; mt < 4; mt++)
        #pragma unroll
        for (int nt = 0; nt < 4; nt++)
          mma16816h(acc[mt][nt], ar[mt], &br[nt>>1][(nt&1)*2]);
    }
    // single sync per chunk: next iteration's barrier orders WAR on stages
  }

  // staged epilogue
  float* sOut = (float*)smem;
  const int lrow = lane >> 2;
  const int lcol = warpN*32 + (lane & 3)*2;
  #pragma unroll
  for (int mt = 0; mt < 4; mt++){
    if (mt == 0) __syncthreads();  // all warps done with mainloop stages
    #pragma unroll
    for (int nt = 0; nt < 4; nt++){
      float* p0 = &sOut[(warpM*16 + lrow    ) * EPI_PITCH + lcol + nt*8];
      float* p1 = &sOut[(warpM*16 + lrow + 8) * EPI_PITCH + lcol + nt*8];
      p0[0] = acc[mt][nt][0]; p0[1] = acc[mt][nt][1];
      p1[0] = acc[mt][nt][2]; p1[1] = acc[mt][nt][3];
    }
    __syncthreads();
    #pragma unroll
    for (int i = 0; i < 4; i++){
      int idx = tid + i * 256;
      int r = idx >> 5, c4 = idx & 31;
      int gr = tileM + (r >> 4) * 64 + mt * 16 + (r & 15);
      float4 val = *(float4*)&sOut[r * EPI_PITCH + c4 * 4];
      if (sizeof(CT) == 4){
        *(float4*)&((float*)Cout)[(size_t)gr * GK + tileN + c4 * 4] = val;
      } else {
        __half2 h0 = __floats2half2_rn(val.x, val.y);
        __half2 h1 = __floats2half2_rn(val.z, val.w);
        uint32_t u0 = *(uint32_t*)&h0, u1 = *(uint32_t*)&h1;
        *(uint2*)&((__half*)Cout)[(size_t)gr * GK + tileN + c4 * 4] = make_uint2(u0, u1);
      }
    }
    __syncthreads();
  }
}

// ---------------------------------------------------------------------------
// fp32 -> fp16
// ---------------------------------------------------------------------------
__global__ void tohalf_kernel(const float* __restrict__ X, __half* __restrict__ H)
{
  int i = (blockIdx.x * 256 + threadIdx.x) * 4;
  float4 xv = *(const float4*)(X + i);
  *(__half2*)(H + i)     = __floats2half2_rn(xv.x, xv.y);
  *(__half2*)(H + i + 2) = __floats2half2_rn(xv.z, xv.w);
}

// ---------------------------------------------------------------------------
// Fused 4-way weight transpose + fp16
// ---------------------------------------------------------------------------
__global__ void wt4_kernel(const float* __restrict__ W0, const float* __restrict__ W1,
                           const float* __restrict__ W2, const float* __restrict__ W3,
                           __half* __restrict__ TH)
{
  const float* W = (blockIdx.z == 0) ? W0 : (blockIdx.z == 1) ? W1 : (blockIdx.z == 2) ? W2 : W3;
  __half* T = TH + (size_t)blockIdx.z * (DD*DD);
  __shared__ float tile[32][33];
  const int n0 = blockIdx.x * 32, k0 = blockIdx.y * 32;
  const int tx = threadIdx.x, ty = threadIdx.y;
  #pragma unroll
  for (int i = 0; i < 4; i++)
    tile[ty + i*8][tx] = W[(size_t)(k0 + ty + i*8) * DD + n0 + tx];
  __syncthreads();
  #pragma unroll
  for (int i = 0; i < 4; i++){
    float v = tile[tx][ty + i*8];
    T[(size_t)(n0 + ty + i*8) * DD + k0 + tx] = __float2half_rn(v);
  }
}

// ---------------------------------------------------------------------------
// beta = sigmoid(x @ Wb)
// ---------------------------------------------------------------------------
__global__ void beta_kernel(const float* __restrict__ x, const float* __restrict__ Wb,
                            float* __restrict__ gb)
{
  const int m = blockIdx.x;
  const int tid = threadIdx.x;
  const int h = tid & 15, part = tid >> 4;
  __shared__ float sx[DD];
  for (int i = tid; i < DD/4; i += 64)
    *(float4*)&sx[i*4] = *(const float4*)&x[(size_t)m * DD + i*4];
  __syncthreads();
  float acc = 0.f;
  const int kbase = part * 256;
  for (int kk = 0; kk < 256; kk++)
    acc += sx[kbase + kk] * Wb[(size_t)(kbase + kk) * HH + h];
  __shared__ float red[64];
  red[tid] = acc;
  __syncthreads();
  if (tid < 16) {
    float s = red[tid] + red[tid+16] + red[tid+32] + red[tid+48];
    int b = m >> 11, t = m & (TT-1);
    gb[((size_t)b * HH + tid) * TT + t] = 1.f / (1.f + __expf(-s));
  }
}

// ---------------------------------------------------------------------------
// Fused conv (fp16 input) + SiLU (+ L2 norm for q,k). [M,D] -> [B,H,T,DH]
// ---------------------------------------------------------------------------
__global__ void conv3_kernel(const __half* __restrict__ Xq, const __half* __restrict__ Xk,
                             const __half* __restrict__ Xv,
                             const float* __restrict__ Wq, const float* __restrict__ Wk,
                             const float* __restrict__ Wv,
                             float* __restrict__ Yq, float* __restrict__ Yk,
                             float* __restrict__ Yv)
{
  const int which = blockIdx.y;
  const __half* X = (which == 0) ? Xq : (which == 1) ? Xk : Xv;
  const float*  W = (which == 0) ? Wq : (which == 1) ? Wk : Wv;
  float*        Y = (which == 0) ? Yq : (which == 1) ? Yk : Yv;
  const bool norm = (which < 2);

  const int m = blockIdx.x;
  const int b = m >> 11, t = m & (TT-1);
  const int tid = threadIdx.x;
  const int c0 = tid * 4;

  float warr[4][4];
  #pragma unroll
  for (int j = 0; j < 4; j++) {
    float4 wv = *(const float4*)&W[(size_t)(c0 + j) * 4];
    warr[j][0] = wv.x; warr[j][1] = wv.y; warr[j][2] = wv.z; warr[j][3] = wv.w;
  }
  float acc[4] = {0.f, 0.f, 0.f, 0.f};
  #pragma unroll
  for (int i = 0; i < 4; i++) {
    int tt = t - 3 + i;
    if (tt >= 0) {
      uint2 raw = *(const uint2*)&X[((size_t)(b * TT + tt)) * DD + c0];
      __half2 h0 = *(__half2*)&raw.x, h1 = *(__half2*)&raw.y;
      float2 f0 = __half22float2(h0), f1 = __half22float2(h1);
      acc[0] += warr[0][i] * f0.x;
      acc[1] += warr[1][i] * f0.y;
      acc[2] += warr[2][i] * f1.x;
      acc[3] += warr[3][i] * f1.y;
    }
  }
  float y[4];
  #pragma unroll
  for (int j = 0; j < 4; j++) {
    float s = 1.f / (1.f + __expf(-acc[j]));
    y[j] = acc[j] * s;
  }
  float scale = 1.f;
  if (norm) {
    float ss = y[0]*y[0] + y[1]*y[1] + y[2]*y[2] + y[3]*y[3];
    #pragma unroll
    for (int off = 8; off > 0; off >>= 1)
      ss += __shfl_xor_sync(0xffffffffu, ss, off, 16);
    scale = rsqrtf(ss + 1e-6f);
  }
  const int h = tid >> 4;
  const int dh0 = (tid & 15) * 4;
  *(float4*)&Y[(((size_t)(b * HH + h)) * TT + t) * DHH + dh0] =
      make_float4(y[0]*scale, y[1]*scale, y[2]*scale, y[3]*scale);
}

// ---------------------------------------------------------------------------
// WY precompute (unchanged)
// ---------------------------------------------------------------------------
#define PRE_K  0
#define PRE_V  4096
#define PRE_Q  8192
#define PRE_KT 12288
#define PRE_A  16640
#define PRE_TI 20736
#define PRE_B  24896
#define PRE_TOT 24960

__global__ __launch_bounds__(256, 1)
void wy_pre(const float* __restrict__ gq, const float* __restrict__ gk,
            const float* __restrict__ gv, const float* __restrict__ gb,
            float* __restrict__ gW, float* __restrict__ gU0, float* __restrict__ gM)
{
  extern __shared__ float sm[];
  const int chunk = blockIdx.x;
  const int bh    = blockIdx.y;
  const int cid   = bh * NC + chunk;
  const int tid   = threadIdx.x;

  const float* K = gk + ((size_t)bh * TT + chunk * CC) * DHH;
  const float* Q = gq + ((size_t)bh * TT + chunk * CC) * DHH;
  const float* V = gv + ((size_t)bh * TT + chunk * CC) * DHH;
  const float* B = gb + (size_t)bh * TT + chunk * CC;

  #pragma unroll
  for (int i = 0; i < 4; i++){
    int idx  = tid + i * 256;
    int row  = idx >> 4, c4 = idx & 15;
    float4 kv = *(const float4*)&K[row * DHH + c4 * 4];
    *(float4*)&sm[PRE_K + row * 64 + c4 * 4] = kv;
    sm[PRE_KT + (c4*4+0) * 68 + row] = kv.x;
    sm[PRE_KT + (c4*4+1) * 68 + row] = kv.y;
    sm[PRE_KT + (c4*4+2) * 68 + row] = kv.z;
    sm[PRE_KT + (c4*4+3) * 68 + row] = kv.w;
    *(float4*)&sm[PRE_Q + row * 64 + c4 * 4] = *(const float4*)&Q[row * DHH + c4 * 4];
    *(float4*)&sm[PRE_V + row * 64 + c4 * 4] = *(const float4*)&V[row * DHH + c4 * 4];
  }
  if (tid < 64) sm[PRE_B + tid] = B[tid];
  for (int i = tid; i < 64*65; i += 256) sm[PRE_TI + i] = 0.f;
  __syncthreads();

  {
    const int ty = tid >> 4, tx = tid & 15;
    const int r0 = ty * 4, c0 = tx * 4;
    unsigned long long accA[4][2], accM[4][2];
    #pragma unroll
    for (int m = 0; m < 4; m++){ accA[m][0]=accA[m][1]=accM[m][0]=accM[m][1]=0ull; }
    #pragma unroll 8
    for (int d = 0; d < 64; d++){
      ulonglong2 kc = *(const ulonglong2*)&sm[PRE_KT + d * 68 + c0];
      #pragma unroll
      for (int m = 0; m < 4; m++){
        unsigned long long kr = dup2(sm[PRE_K + (r0+m)*64 + d]);
        unsigned long long qr = dup2(sm[PRE_Q + (r0+m)*64 + d]);
        ffma2(accA[m][0], kr, kc.x);  ffma2(accA[m][1], kr, kc.y);
        ffma2(accM[m][0], qr, kc.x);  ffma2(accM[m][1], qr, kc.y);
      }
    }
    float* Mout = gM + (size_t)cid * (CC*CC);
    #pragma unroll
    for (int m = 0; m < 4; m++){
      const int t = r0 + m;
      const float bt = sm[PRE_B + t];
      float2 a01 = unpk2(accA[m][0]), a23 = unpk2(accA[m][1]);
      float2 m01 = unpk2(accM[m][0]), m23 = unpk2(accM[m][1]);
      float av[4] = {a01.x, a01.y, a23.x, a23.y};
      float mv[4] = {m01.x, m01.y, m23.x, m23.y};
      #pragma unroll
      for (int i = 0; i < 4; i++){
        const int s = c0 + i;
        sm[PRE_A + t*64 + s] = (s < t) ? bt * av[i] : 0.f;
        Mout[t*64 + s]       = (s <= t) ? mv[i] : 0.f;
      }
    }
  }
  __syncthreads();

  if (tid < 64){
    const int c = tid;
    sm[PRE_TI + c*65 + c] = 1.f;
    for (int t = c + 1; t < 64; t++){
      float acc = 0.f;
      for (int j = c; j < t; j++)
        acc += sm[PRE_A + t*64 + j] * sm[PRE_TI + j*65 + c];
      sm[PRE_TI + t*65 + c] = -acc;
    }
  }
  __syncthreads();

  {
    const int ty = tid >> 4, tx = tid & 15;
    const int r0 = ty * 4, c0 = tx * 4;
    unsigned long long accW[4][2], accU[4][2];
    #pragma unroll
    for (int m = 0; m < 4; m++){ accW[m][0]=accW[m][1]=accU[m][0]=accU[m][1]=0ull; }
    #pragma unroll 8
    for (int j = 0; j < 64; j++){
      const float bj = sm[PRE_B + j];
      ulonglong2 k2 = *(const ulonglong2*)&sm[PRE_K + j*64 + c0];
      ulonglong2 v2 = *(const ulonglong2*)&sm[PRE_V + j*64 + c0];
      #pragma unroll
      for (int m = 0; m < 4; m++){
        unsigned long long tb = dup2(sm[PRE_TI + (r0+m)*65 + j] * bj);
        ffma2(accW[m][0], tb, k2.x);  ffma2(accW[m][1], tb, k2.y);
        ffma2(accU[m][0], tb, v2.x);  ffma2(accU[m][1], tb, v2.y);
      }
    }
    float* Wout = gW  + (size_t)cid * (CC*DHH);
    float* Uout = gU0 + (size_t)cid * (CC*DHH);
    #pragma unroll
    for (int m = 0; m < 4; m++){
      const int t = r0 + m;
      float2 w01 = unpk2(accW[m][0]), w23 = unpk2(accW[m][1]);
      float2 u01 = unpk2(accU[m][0]), u23 = unpk2(accU[m][1]);
      *(float4*)&Wout[t*64 + c0] = make_float4(w01.x, w01.y, w23.x, w23.y);
      *(float4*)&Uout[t*64 + c0] = make_float4(u01.x, u01.y, u23.x, u23.y);
    }
  }
}

// ---------------------------------------------------------------------------
// WY sequential pass v2: smem-staged operands via double-buffered cp.async.
// smem (floats): per stage {W,M,Q,K pitch 68 rows=64; U0 16 cols} = 18432,
// 2 stages + sS/sU (pitch 20) => 39424 floats = 157696 B.
// ---------------------------------------------------------------------------
#define SP 20
#define SEQ_W  0
#define SEQ_M  4352
#define SEQ_Q  8704
#define SEQ_K  13056
#define SEQ_U0 17408
#define SEQ_STAGE 18432
#define SEQ_SS (2*SEQ_STAGE)
#define SEQ_SU (SEQ_SS + 64*SP)
#define SEQ_TOT (SEQ_SU + 64*SP)     // 39424 floats

__global__ __launch_bounds__(256, 1)
void wy_seq(const float* __restrict__ gq, const float* __restrict__ gk,
            const float* __restrict__ gW, const float* __restrict__ gU0,
            const float* __restrict__ gM, float* __restrict__ go)
{
  extern __shared__ float sm[];
  const uint32_t sb = smem_u32(sm);
  const int vsplit = blockIdx.x;
  const int bh     = blockIdx.y;
  const int colb   = vsplit * 16;
  const int tid    = threadIdx.x;
  const int trow   = tid >> 2;
  const int vo     = (tid & 3) * 4;

  float* sS = sm + SEQ_SS;
  float* sU = sm + SEQ_SU;

  // stage loader: W/M/Q/K 1024 float4-chunks each, U0 256 chunks => 4608, 18/thread
  auto load_chunk = [&](int st, int c){
    const size_t cid = (size_t)bh * NC + c;
    const float* srcs[4] = { gW + cid * (CC*DHH), gM + cid * (CC*CC),
                             gq + ((size_t)bh * TT + c * CC) * DHH,
                             gk + ((size_t)bh * TT + c * CC) * DHH };
    const uint32_t stb = sb + (st * SEQ_STAGE) * 4;
    #pragma unroll
    for (int i = 0; i < 16; i++){
      int id = tid + i * 256;            // 0..4095
      int mat = id >> 10, rem = id & 1023;
      int row = rem >> 4, c4 = rem & 15;
      cpasync16(stb + (mat * 4352 + row * 68 + c4 * 4) * 4,
                srcs[mat] + (size_t)row * 64 + c4 * 4);
    }
    {
      int id = tid + 4096;               // 4096..4351 -> U0 (first 256 ids)
      int rem = id - 4096;               // == tid
      int row = rem >> 2, c4 = rem & 3;
      cpasync16(stb + (SEQ_U0 + row * 16 + c4 * 4) * 4,
                gU0 + cid * (CC*DHH) + (size_t)row * 64 + colb + c4 * 4);
    }
    (void)0;
  };
  // note: ids 0..4095 cover W,M,Q,K; the extra 256 (one per thread) covers U0.

  for (int i = tid; i < 64 * SP; i += 256){ sS[i] = 0.f; }
  load_chunk(0, 0); cpasync_commit();
  __syncthreads();

  for (int c = 0; c < NC; c++){
    const int st = c & 1;
    if (c + 1 < NC){ load_chunk(st ^ 1, c + 1); cpasync_commit();
                     asm volatile("cp.async.wait_group 1;" ::: "memory"); }
    else           { asm volatile("cp.async.wait_group 0;" ::: "memory"); }
    __syncthreads();

    const float* cW  = sm + st * SEQ_STAGE + SEQ_W;
    const float* cM  = sm + st * SEQ_STAGE + SEQ_M;
    const float* cQ  = sm + st * SEQ_STAGE + SEQ_Q;
    const float* cK  = sm + st * SEQ_STAGE + SEQ_K;
    const float* cU0 = sm + st * SEQ_STAGE + SEQ_U0;
    float* Op = go + ((size_t)bh * TT + c * CC) * DHH + colb;

    // phase 1: U = U0 - W S
    {
      float4 u0 = *(const float4*)&cU0[trow*16 + vo];
      unsigned long long a0, a1;
      { unsigned lo0=__float_as_uint(u0.x), hi0=__float_as_uint(u0.y);
        unsigned lo1=__float_as_uint(u0.z), hi1=__float_as_uint(u0.w);
        asm("mov.b64 %0, {%1, %2};" : "=l"(a0) : "r"(lo0), "r"(hi0));
        asm("mov.b64 %0, {%1, %2};" : "=l"(a1) : "r"(lo1), "r"(hi1)); }
      #pragma unroll 8
      for (int kk = 0; kk < 64; kk++){
        unsigned long long nw = dup2(-cW[trow*68 + kk]);
        ulonglong2 s2 = *(const ulonglong2*)&sS[kk*SP + vo];
        ffma2(a0, nw, s2.x);  ffma2(a1, nw, s2.y);
      }
      *(ulonglong2*)&sU[trow*SP + vo] = make_ulonglong2(a0, a1);
    }
    __syncthreads();

    // phase 2: O = Q S + M U
    {
      unsigned long long a0 = 0ull, a1 = 0ull;
      #pragma unroll 8
      for (int j = 0; j < 64; j++){
        unsigned long long qd = dup2(cQ[trow*68 + j]);
        ulonglong2 s2 = *(const ulonglong2*)&sS[j*SP + vo];
        ffma2(a0, qd, s2.x);  ffma2(a1, qd, s2.y);
      }
      #pragma unroll 8
      for (int s = 0; s < 64; s++){
        unsigned long long md = dup2(cM[trow*68 + s]);
        ulonglong2 u2 = *(const ulonglong2*)&sU[s*SP + vo];
        ffma2(a0, md, u2.x);  ffma2(a1, md, u2.y);
      }
      float2 o01 = unpk2(a0), o23 = unpk2(a1);
      *(float4*)&Op[trow*64 + vo] = make_float4(o01.x, o01.y, o23.x, o23.y);
    }
    __syncthreads();

    // phase 3: S += K^T U
    {
      ulonglong2 sacc = *(const ulonglong2*)&sS[trow*SP + vo];
      unsigned long long a0 = sacc.x, a1 = sacc.y;
      #pragma unroll 8
      for (int t = 0; t < 64; t++){
        unsigned long long kd = dup2(cK[t*68 + trow]);
        ulonglong2 u2 = *(const ulonglong2*)&sU[t*SP + vo];
        ffma2(a0, kd, u2.x);  ffma2(a1, kd, u2.y);
      }
      *(ulonglong2*)&sS[trow*SP + vo] = make_ulonglong2(a0, a1);
    }
    __syncthreads();
  }
}

// ---------------------------------------------------------------------------
// Per-head RMSNorm * rms_g -> [M,D] fp16
// ---------------------------------------------------------------------------
__global__ void rmsnorm_kernel(const float* __restrict__ O, const float* __restrict__ g,
                               __half* __restrict__ YH)
{
  const int m = blockIdx.x;
  const int b = m >> 11, t = m & (TT-1);
  const int tid = threadIdx.x;
  const int h = tid >> 4;
  const int dh0 = (tid & 15) * 4;

  float4 ov = *(const float4*)&O[(((size_t)(b * HH + h)) * TT + t) * DHH + dh0];
  float ss = ov.x*ov.x + ov.y*ov.y + ov.z*ov.z + ov.w*ov.w;
  #pragma unroll
  for (int off = 8; off > 0; off >>= 1)
    ss += __shfl_xor_sync(0xffffffffu, ss, off, 16);
  float sc = rsqrtf(ss * (1.f / 64.f) + 1e-6f);
  float4 gv = *(const float4*)&g[dh0];
  size_t base = (size_t)m * DD + tid * 4;
  *(__half2*)(YH + base)     = __floats2half2_rn(ov.x * sc * gv.x, ov.y * sc * gv.y);
  *(__half2*)(YH + base + 2) = __floats2half2_rn(ov.z * sc * gv.z, ov.w * sc * gv.w);
}

// ---------------------------------------------------------------------------
// Launch
// ---------------------------------------------------------------------------
extern "C" void kernel_launch(void* const* d_in, const int* in_sizes, int n_in,
                              void* d_out, int out_size)
{
  (void)in_sizes; (void)n_in; (void)out_size;
  const float* x  = (const float*)d_in[0];
  const float* Wq = (const float*)d_in[1];
  const float* Wk = (const float*)d_in[2];
  const float* Wv = (const float*)d_in[3];
  const float* Wb = (const float*)d_in[4];
  const float* cq = (const float*)d_in[5];
  const float* ck = (const float*)d_in[6];
  const float* cv = (const float*)d_in[7];
  const float* rg = (const float*)d_in[8];
  const float* Wo = (const float*)d_in[9];
  float* out = (float*)d_out;

  float *q, *k, *v, *beta, *o, *gW, *gU0, *gM;
  __half *qch, *kch, *vch, *xh, *oh, *wt;
  cudaGetSymbolAddress((void**)&qch, g_qch);
  cudaGetSymbolAddress((void**)&kch, g_kch);
  cudaGetSymbolAddress((void**)&vch, g_vch);
  cudaGetSymbolAddress((void**)&q,   g_q);
  cudaGetSymbolAddress((void**)&k,   g_k);
  cudaGetSymbolAddress((void**)&v,   g_v);
  cudaGetSymbolAddress((void**)&beta, g_beta);
  cudaGetSymbolAddress((void**)&o,   g_o);
  cudaGetSymbolAddress((void**)&gW,  g_W);
  cudaGetSymbolAddress((void**)&gU0, g_U0);
  cudaGetSymbolAddress((void**)&gM,  g_M);
  cudaGetSymbolAddress((void**)&xh,  g_xh);
  cudaGetSymbolAddress((void**)&oh,  g_oh);
  cudaGetSymbolAddress((void**)&wt,  g_wt);

  cudaFuncSetAttribute(gemm_mma<__half>, cudaFuncAttributeMaxDynamicSharedMemorySize, GEMM_SMEM);
  cudaFuncSetAttribute(gemm_mma<float>,  cudaFuncAttributeMaxDynamicSharedMemorySize, GEMM_SMEM);
  cudaFuncSetAttribute(wy_pre, cudaFuncAttributeMaxDynamicSharedMemorySize, PRE_TOT * 4);
  cudaFuncSetAttribute(wy_seq, cudaFuncAttributeMaxDynamicSharedMemorySize, SEQ_TOT * 4);

  const size_t WSZ = (size_t)DD * DD;

  tohalf_kernel<<<MM * DD / 1024, 256>>>(x, xh);
  wt4_kernel<<<dim3(32, 32, 4), dim3(32, 8)>>>(Wq, Wk, Wv, Wo, wt);

  gemm_mma<__half><<<dim3(24, MM/128), 256, GEMM_SMEM>>>(xh, wt, qch, kch, vch);

  beta_kernel<<<MM, 64>>>(x, Wb, beta);
  conv3_kernel<<<dim3(MM, 3), 256>>>(qch, kch, vch, cq, ck, cv, q, k, v);

  wy_pre<<<dim3(NC, NBH), 256, PRE_TOT * 4>>>(q, k, v, beta, gW, gU0, gM);
  wy_seq<<<dim3(4, NBH), 256, SEQ_TOT * 4>>>(q, k, gW, gU0, gM, o);

  rmsnorm_kernel<<<MM, 256>>>(o, rg, oh);
  gemm_mma<float><<<dim3(8, MM/128), 256, GEMM_SMEM>>>(oh, wt + 3*WSZ, out, out, out);
}

// round 12
// speedup vs baseline: 3.4796x; 1.0314x over previous
#include <cuda_runtime.h>
#include <cuda_fp16.h>
#include <cstdint>

// Problem constants
#define BB 2
#define TT 2048
#define DD 1024
#define HH 16
#define DHH 64
#define MM (BB*TT)
#define CC 64
#define NC (TT/CC)
#define NBH (BB*HH)
#define NCHT (NBH*NC)

// ---------------------------------------------------------------------------
// Scratch
// ---------------------------------------------------------------------------
__device__ __half g_qch[MM*DD];
__device__ __half g_kch[MM*DD];
__device__ __half g_vch[MM*DD];
__device__ float g_q [MM*DD];
__device__ float g_k [MM*DD];
__device__ float g_v [MM*DD];
__device__ float g_beta[BB*HH*TT];
__device__ float g_o [MM*DD];

__device__ float g_W [NCHT*CC*DHH];
__device__ float g_U0[NCHT*CC*DHH];
__device__ float g_M [NCHT*CC*CC];

__device__ __half g_xh[MM*DD];
__device__ __half g_oh[MM*DD];
__device__ __half g_wt[4][DD*DD];
__device__ float  g_wbt[HH*DD];     // Wb^T [16][1024]

// ---------------------------------------------------------------------------
// f32x2 helpers
// ---------------------------------------------------------------------------
__device__ __forceinline__ unsigned long long dup2(float x){
  unsigned long long r;
  unsigned u = __float_as_uint(x);
  asm("mov.b64 %0, {%1, %1};" : "=l"(r) : "r"(u));
  return r;
}
__device__ __forceinline__ void ffma2(unsigned long long &c, unsigned long long a, unsigned long long b){
  asm("fma.rn.f32x2 %0, %1, %2, %0;" : "+l"(c) : "l"(a), "l"(b));
}
__device__ __forceinline__ float2 unpk2(unsigned long long p){
  unsigned lo, hi;
  asm("mov.b64 {%0, %1}, %2;" : "=r"(lo), "=r"(hi) : "l"(p));
  return make_float2(__uint_as_float(lo), __uint_as_float(hi));
}

// ---------------------------------------------------------------------------
// smem / cp.async / mma helpers
// ---------------------------------------------------------------------------
__device__ __forceinline__ uint32_t smem_u32(const void* p){
  uint32_t a;
  asm("{ .reg .u64 t; cvta.to.shared.u64 t, %1; cvt.u32.u64 %0, t; }" : "=r"(a) : "l"(p));
  return a;
}
__device__ __forceinline__ void cpasync16(uint32_t dst, const void* src){
  asm volatile("cp.async.cg.shared.global [%0], [%1], 16;" :: "r"(dst), "l"(src));
}
__device__ __forceinline__ void cpasync_commit(){
  asm volatile("cp.async.commit_group;" ::: "memory");
}
__device__ __forceinline__ void ldm4(uint32_t* r, uint32_t addr){
  asm volatile("ldmatrix.sync.aligned.m8n8.x4.shared.b16 {%0,%1,%2,%3}, [%4];"
               : "=r"(r[0]), "=r"(r[1]), "=r"(r[2]), "=r"(r[3]) : "r"(addr));
}
__device__ __forceinline__ void mma16816h(float* d, const uint32_t* a, const uint32_t* b){
  asm volatile(
    "mma.sync.aligned.m16n8k16.row.col.f32.f16.f16.f32 "
    "{%0,%1,%2,%3}, {%4,%5,%6,%7}, {%8,%9}, {%0,%1,%2,%3};"
    : "+f"(d[0]), "+f"(d[1]), "+f"(d[2]), "+f"(d[3])
    : "r"(a[0]), "r"(a[1]), "r"(a[2]), "r"(a[3]), "r"(b[0]), "r"(b[1]));
}

// ---------------------------------------------------------------------------
// fp16 GEMM: KC=64, 3-stage cp.async (2 CTAs/SM), one sync/chunk, staged epi.
// ---------------------------------------------------------------------------
#define GK   1024
#define KC   64
#define NCHG (GK/KC)           // 16
#define ROWB 144               // 64 fp16 (128B) + 16B pad; 9 mod 8 coprime -> conflict-free
#define MATB (128*ROWB)        // 18432
#define STAGEB (2*MATB)        // 36864
#define NSTAGE 3
#define GEMM_SMEM (NSTAGE*STAGEB)   // 110592
#define EPI_PITCH 132

template<typename CT>
__global__ __launch_bounds__(256, 2)
void gemm_mma(const __half* __restrict__ A, const __half* __restrict__ Bbase,
              CT* __restrict__ C0, CT* __restrict__ C1, CT* __restrict__ C2)
{
  extern __shared__ char smem[];
  const uint32_t sb = smem_u32(smem);
  const int tid   = threadIdx.x;
  const int wid   = tid >> 5;
  const int lane  = tid & 31;
  const int warpM = wid & 1;
  const int warpN = wid >> 1;
  const int proj  = blockIdx.x >> 3;
  const int tileN = (blockIdx.x & 7) * 128;
  const int tileM = blockIdx.y * 128;
  const __half* B = Bbase + (size_t)proj * (DD*DD);
  CT* Cout = (proj == 0) ? C0 : ((proj == 1) ? C1 : C2);

  const __half* gsrc[2] = { A + (size_t)tileM * GK, B + (size_t)tileN * GK };

  // 2 mats x 128 rows x 8 chunks(16B) = 2048 chunks, 8/thread
  auto load_stage = [&](int s, int kt){
    const uint32_t base = sb + s * STAGEB;
    #pragma unroll
    for (int i = 0; i < 8; i++){
      int cid = tid + i * 256;
      int mat = cid >> 10;
      int rem = cid & 1023;
      int row = rem >> 3, ch = rem & 7;
      cpasync16(base + mat * MATB + row * ROWB + ch * 16,
                gsrc[mat] + (size_t)row * GK + kt + ch * 8);
    }
  };

  float acc[4][4][4];
  #pragma unroll
  for (int mt = 0; mt < 4; mt++)
    #pragma unroll
    for (int nt = 0; nt < 4; nt++)
      #pragma unroll
      for (int j = 0; j < 4; j++) acc[mt][nt][j] = 0.f;

  const int aRow   = lane & 15;
  const int aKhalf = lane >> 4;
  const uint32_t aOff = (uint32_t)(warpM*64 + aRow) * ROWB + aKhalf * 16;
  const int bRow   = (lane & 7) + ((lane >> 4) << 3);
  const int bKhalf = (lane >> 3) & 1;
  const uint32_t bOff = (uint32_t)(warpN*32 + bRow) * ROWB + bKhalf * 16;

  load_stage(0, 0);    cpasync_commit();
  load_stage(1, KC);   cpasync_commit();

  for (int c = 0; c < NCHG; c++){
    if (c < NCHG - 1) asm volatile("cp.async.wait_group 1;" ::: "memory");
    else              asm volatile("cp.async.wait_group 0;" ::: "memory");
    __syncthreads();

    if (c + 2 < NCHG){
      int s = (c + 2) % 3;
      load_stage(s, (c + 2) * KC);
      cpasync_commit();
    }

    const uint32_t sbuf = sb + (c % 3) * STAGEB;
    #pragma unroll
    for (int ks = 0; ks < 4; ks++){
      const uint32_t koff = ks * 32;
      uint32_t ar[4][4], br[2][4];
      #pragma unroll
      for (int mt = 0; mt < 4; mt++)
        ldm4(ar[mt], sbuf + 0*MATB + aOff + mt*16*ROWB + koff);
      #pragma unroll
      for (int p = 0; p < 2; p++)
        ldm4(br[p], sbuf + 1*MATB + bOff + p*16*ROWB + koff);
      #pragma unroll
      for (int mt = 0; mt < 4; mt++)
        #pragma unroll
        for (int nt = 0; nt < 4; nt++)
          mma16816h(acc[mt][nt], ar[mt], &br[nt>>1][(nt&1)*2]);
    }
  }

  // staged epilogue
  float* sOut = (float*)smem;
  const int lrow = lane >> 2;
  const int lcol = warpN*32 + (lane & 3)*2;
  #pragma unroll
  for (int mt = 0; mt < 4; mt++){
    if (mt == 0) __syncthreads();
    #pragma unroll
    for (int nt = 0; nt < 4; nt++){
      float* p0 = &sOut[(warpM*16 + lrow    ) * EPI_PITCH + lcol + nt*8];
      float* p1 = &sOut[(warpM*16 + lrow + 8) * EPI_PITCH + lcol + nt*8];
      p0[0] = acc[mt][nt][0]; p0[1] = acc[mt][nt][1];
      p1[0] = acc[mt][nt][2]; p1[1] = acc[mt][nt][3];
    }
    __syncthreads();
    #pragma unroll
    for (int i = 0; i < 4; i++){
      int idx = tid + i * 256;
      int r = idx >> 5, c4 = idx & 31;
      int gr = tileM + (r >> 4) * 64 + mt * 16 + (r & 15);
      float4 val = *(float4*)&sOut[r * EPI_PITCH + c4 * 4];
      if (sizeof(CT) == 4){
        *(float4*)&((float*)Cout)[(size_t)gr * GK + tileN + c4 * 4] = val;
      } else {
        __half2 h0 = __floats2half2_rn(val.x, val.y);
        __half2 h1 = __floats2half2_rn(val.z, val.w);
        uint32_t u0 = *(uint32_t*)&h0, u1 = *(uint32_t*)&h1;
        *(uint2*)&((__half*)Cout)[(size_t)gr * GK + tileN + c4 * 4] = make_uint2(u0, u1);
      }
    }
    __syncthreads();
  }
}

// ---------------------------------------------------------------------------
// fp32 -> fp16
// ---------------------------------------------------------------------------
__global__ void tohalf_kernel(const float* __restrict__ X, __half* __restrict__ H)
{
  int i = (blockIdx.x * 256 + threadIdx.x) * 4;
  float4 xv = *(const float4*)(X + i);
  *(__half2*)(H + i)     = __floats2half2_rn(xv.x, xv.y);
  *(__half2*)(H + i + 2) = __floats2half2_rn(xv.z, xv.w);
}

// ---------------------------------------------------------------------------
// Fused 4-way weight transpose + fp16
// ---------------------------------------------------------------------------
__global__ void wt4_kernel(const float* __restrict__ W0, const float* __restrict__ W1,
                           const float* __restrict__ W2, const float* __restrict__ W3,
                           __half* __restrict__ TH)
{
  const float* W = (blockIdx.z == 0) ? W0 : (blockIdx.z == 1) ? W1 : (blockIdx.z == 2) ? W2 : W3;
  __half* T = TH + (size_t)blockIdx.z * (DD*DD);
  __shared__ float tile[32][33];
  const int n0 = blockIdx.x * 32, k0 = blockIdx.y * 32;
  const int tx = threadIdx.x, ty = threadIdx.y;
  #pragma unroll
  for (int i = 0; i < 4; i++)
    tile[ty + i*8][tx] = W[(size_t)(k0 + ty + i*8) * DD + n0 + tx];
  __syncthreads();
  #pragma unroll
  for (int i = 0; i < 4; i++){
    float v = tile[tx][ty + i*8];
    T[(size_t)(n0 + ty + i*8) * DD + k0 + tx] = __float2half_rn(v);
  }
}

// ---------------------------------------------------------------------------
// Wb [1024][16] -> WbT [16][1024]
// ---------------------------------------------------------------------------
__global__ void wbt_kernel(const float* __restrict__ Wb, float* __restrict__ T)
{
  int idx = blockIdx.x * 256 + threadIdx.x;   // 0..16383
  int k = idx >> 4, h = idx & 15;
  T[h * DD + k] = Wb[idx];
}

// ---------------------------------------------------------------------------
// beta v2: warp-per-row GEMV vs WbT (L1-resident), butterfly reduce.
// ---------------------------------------------------------------------------
__global__ __launch_bounds__(256)
void beta_kernel(const float* __restrict__ x, const float* __restrict__ WbT,
                 float* __restrict__ gb)
{
  const int w = threadIdx.x >> 5, lane = threadIdx.x & 31;
  const int m = blockIdx.x * 8 + w;
  const float* xr = x + (size_t)m * DD;

  float4 xv[8];
  #pragma unroll
  for (int i = 0; i < 8; i++) xv[i] = *(const float4*)&xr[lane*4 + i*128];

  float mine = 0.f;
  #pragma unroll
  for (int h = 0; h < 16; h++){
    const float* wr = WbT + h * DD;
    float acc = 0.f;
    #pragma unroll
    for (int i = 0; i < 8; i++){
      float4 wv = *(const float4*)&wr[lane*4 + i*128];
      acc += xv[i].x*wv.x + xv[i].y*wv.y + xv[i].z*wv.z + xv[i].w*wv.w;
    }
    #pragma unroll
    for (int off = 16; off > 0; off >>= 1)
      acc += __shfl_xor_sync(0xffffffffu, acc, off);
    if (lane == h) mine = acc;
  }
  if (lane < 16){
    int b = m >> 11, t = m & (TT-1);
    gb[((size_t)b * HH + lane) * TT + t] = 1.f / (1.f + __expf(-mine));
  }
}

// ---------------------------------------------------------------------------
// Fused conv (fp16 input) + SiLU (+ L2 norm for q,k). [M,D] -> [B,H,T,DH]
// ---------------------------------------------------------------------------
__global__ void conv3_kernel(const __half* __restrict__ Xq, const __half* __restrict__ Xk,
                             const __half* __restrict__ Xv,
                             const float* __restrict__ Wq, const float* __restrict__ Wk,
                             const float* __restrict__ Wv,
                             float* __restrict__ Yq, float* __restrict__ Yk,
                             float* __restrict__ Yv)
{
  const int which = blockIdx.y;
  const __half* X = (which == 0) ? Xq : (which == 1) ? Xk : Xv;
  const float*  W = (which == 0) ? Wq : (which == 1) ? Wk : Wv;
  float*        Y = (which == 0) ? Yq : (which == 1) ? Yk : Yv;
  const bool norm = (which < 2);

  const int m = blockIdx.x;
  const int b = m >> 11, t = m & (TT-1);
  const int tid = threadIdx.x;
  const int c0 = tid * 4;

  float warr[4][4];
  #pragma unroll
  for (int j = 0; j < 4; j++) {
    float4 wv = *(const float4*)&W[(size_t)(c0 + j) * 4];
    warr[j][0] = wv.x; warr[j][1] = wv.y; warr[j][2] = wv.z; warr[j][3] = wv.w;
  }
  float acc[4] = {0.f, 0.f, 0.f, 0.f};
  #pragma unroll
  for (int i = 0; i < 4; i++) {
    int tt = t - 3 + i;
    if (tt >= 0) {
      uint2 raw = *(const uint2*)&X[((size_t)(b * TT + tt)) * DD + c0];
      __half2 h0 = *(__half2*)&raw.x, h1 = *(__half2*)&raw.y;
      float2 f0 = __half22float2(h0), f1 = __half22float2(h1);
      acc[0] += warr[0][i] * f0.x;
      acc[1] += warr[1][i] * f0.y;
      acc[2] += warr[2][i] * f1.x;
      acc[3] += warr[3][i] * f1.y;
    }
  }
  float y[4];
  #pragma unroll
  for (int j = 0; j < 4; j++) {
    float s = 1.f / (1.f + __expf(-acc[j]));
    y[j] = acc[j] * s;
  }
  float scale = 1.f;
  if (norm) {
    float ss = y[0]*y[0] + y[1]*y[1] + y[2]*y[2] + y[3]*y[3];
    #pragma unroll
    for (int off = 8; off > 0; off >>= 1)
      ss += __shfl_xor_sync(0xffffffffu, ss, off, 16);
    scale = rsqrtf(ss + 1e-6f);
  }
  const int h = tid >> 4;
  const int dh0 = (tid & 15) * 4;
  *(float4*)&Y[(((size_t)(b * HH + h)) * TT + t) * DHH + dh0] =
      make_float4(y[0]*scale, y[1]*scale, y[2]*scale, y[3]*scale);
}

// ---------------------------------------------------------------------------
// WY precompute (unchanged)
// ---------------------------------------------------------------------------
#define PRE_K  0
#define PRE_V  4096
#define PRE_Q  8192
#define PRE_KT 12288
#define PRE_A  16640
#define PRE_TI 20736
#define PRE_B  24896
#define PRE_TOT 24960

__global__ __launch_bounds__(256, 1)
void wy_pre(const float* __restrict__ gq, const float* __restrict__ gk,
            const float* __restrict__ gv, const float* __restrict__ gb,
            float* __restrict__ gW, float* __restrict__ gU0, float* __restrict__ gM)
{
  extern __shared__ float sm[];
  const int chunk = blockIdx.x;
  const int bh    = blockIdx.y;
  const int cid   = bh * NC + chunk;
  const int tid   = threadIdx.x;

  const float* K = gk + ((size_t)bh * TT + chunk * CC) * DHH;
  const float* Q = gq + ((size_t)bh * TT + chunk * CC) * DHH;
  const float* V = gv + ((size_t)bh * TT + chunk * CC) * DHH;
  const float* B = gb + (size_t)bh * TT + chunk * CC;

  #pragma unroll
  for (int i = 0; i < 4; i++){
    int idx  = tid + i * 256;
    int row  = idx >> 4, c4 = idx & 15;
    float4 kv = *(const float4*)&K[row * DHH + c4 * 4];
    *(float4*)&sm[PRE_K + row * 64 + c4 * 4] = kv;
    sm[PRE_KT + (c4*4+0) * 68 + row] = kv.x;
    sm[PRE_KT + (c4*4+1) * 68 + row] = kv.y;
    sm[PRE_KT + (c4*4+2) * 68 + row] = kv.z;
    sm[PRE_KT + (c4*4+3) * 68 + row] = kv.w;
    *(float4*)&sm[PRE_Q + row * 64 + c4 * 4] = *(const float4*)&Q[row * DHH + c4 * 4];
    *(float4*)&sm[PRE_V + row * 64 + c4 * 4] = *(const float4*)&V[row * DHH + c4 * 4];
  }
  if (tid < 64) sm[PRE_B + tid] = B[tid];
  for (int i = tid; i < 64*65; i += 256) sm[PRE_TI + i] = 0.f;
  __syncthreads();

  {
    const int ty = tid >> 4, tx = tid & 15;
    const int r0 = ty * 4, c0 = tx * 4;
    unsigned long long accA[4][2], accM[4][2];
    #pragma unroll
    for (int m = 0; m < 4; m++){ accA[m][0]=accA[m][1]=accM[m][0]=accM[m][1]=0ull; }
    #pragma unroll 8
    for (int d = 0; d < 64; d++){
      ulonglong2 kc = *(const ulonglong2*)&sm[PRE_KT + d * 68 + c0];
      #pragma unroll
      for (int m = 0; m < 4; m++){
        unsigned long long kr = dup2(sm[PRE_K + (r0+m)*64 + d]);
        unsigned long long qr = dup2(sm[PRE_Q + (r0+m)*64 + d]);
        ffma2(accA[m][0], kr, kc.x);  ffma2(accA[m][1], kr, kc.y);
        ffma2(accM[m][0], qr, kc.x);  ffma2(accM[m][1], qr, kc.y);
      }
    }
    float* Mout = gM + (size_t)cid * (CC*CC);
    #pragma unroll
    for (int m = 0; m < 4; m++){
      const int t = r0 + m;
      const float bt = sm[PRE_B + t];
      float2 a01 = unpk2(accA[m][0]), a23 = unpk2(accA[m][1]);
      float2 m01 = unpk2(accM[m][0]), m23 = unpk2(accM[m][1]);
      float av[4] = {a01.x, a01.y, a23.x, a23.y};
      float mv[4] = {m01.x, m01.y, m23.x, m23.y};
      #pragma unroll
      for (int i = 0; i < 4; i++){
        const int s = c0 + i;
        sm[PRE_A + t*64 + s] = (s < t) ? bt * av[i] : 0.f;
        Mout[t*64 + s]       = (s <= t) ? mv[i] : 0.f;
      }
    }
  }
  __syncthreads();

  if (tid < 64){
    const int c = tid;
    sm[PRE_TI + c*65 + c] = 1.f;
    for (int t = c + 1; t < 64; t++){
      float acc = 0.f;
      for (int j = c; j < t; j++)
        acc += sm[PRE_A + t*64 + j] * sm[PRE_TI + j*65 + c];
      sm[PRE_TI + t*65 + c] = -acc;
    }
  }
  __syncthreads();

  {
    const int ty = tid >> 4, tx = tid & 15;
    const int r0 = ty * 4, c0 = tx * 4;
    unsigned long long accW[4][2], accU[4][2];
    #pragma unroll
    for (int m = 0; m < 4; m++){ accW[m][0]=accW[m][1]=accU[m][0]=accU[m][1]=0ull; }
    #pragma unroll 8
    for (int j = 0; j < 64; j++){
      const float bj = sm[PRE_B + j];
      ulonglong2 k2 = *(const ulonglong2*)&sm[PRE_K + j*64 + c0];
      ulonglong2 v2 = *(const ulonglong2*)&sm[PRE_V + j*64 + c0];
      #pragma unroll
      for (int m = 0; m < 4; m++){
        unsigned long long tb = dup2(sm[PRE_TI + (r0+m)*65 + j] * bj);
        ffma2(accW[m][0], tb, k2.x);  ffma2(accW[m][1], tb, k2.y);
        ffma2(accU[m][0], tb, v2.x);  ffma2(accU[m][1], tb, v2.y);
      }
    }
    float* Wout = gW  + (size_t)cid * (CC*DHH);
    float* Uout = gU0 + (size_t)cid * (CC*DHH);
    #pragma unroll
    for (int m = 0; m < 4; m++){
      const int t = r0 + m;
      float2 w01 = unpk2(accW[m][0]), w23 = unpk2(accW[m][1]);
      float2 u01 = unpk2(accU[m][0]), u23 = unpk2(accU[m][1]);
      *(float4*)&Wout[t*64 + c0] = make_float4(w01.x, w01.y, w23.x, w23.y);
      *(float4*)&Uout[t*64 + c0] = make_float4(u01.x, u01.y, u23.x, u23.y);
    }
  }
}

// ---------------------------------------------------------------------------
// WY sequential pass (unchanged from 532us version)
// ---------------------------------------------------------------------------
#define SP 20
#define SEQ_W  0
#define SEQ_M  4352
#define SEQ_Q  8704
#define SEQ_K  13056
#define SEQ_U0 17408
#define SEQ_STAGE 18432
#define SEQ_SS (2*SEQ_STAGE)
#define SEQ_SU (SEQ_SS + 64*SP)
#define SEQ_TOT (SEQ_SU + 64*SP)

__global__ __launch_bounds__(256, 1)
void wy_seq(const float* __restrict__ gq, const float* __restrict__ gk,
            const float* __restrict__ gW, const float* __restrict__ gU0,
            const float* __restrict__ gM, float* __restrict__ go)
{
  extern __shared__ float sm[];
  const uint32_t sb = smem_u32(sm);
  const int vsplit = blockIdx.x;
  const int bh     = blockIdx.y;
  const int colb   = vsplit * 16;
  const int tid    = threadIdx.x;
  const int trow   = tid >> 2;
  const int vo     = (tid & 3) * 4;

  float* sS = sm + SEQ_SS;
  float* sU = sm + SEQ_SU;

  auto load_chunk = [&](int st, int c){
    const size_t cid = (size_t)bh * NC + c;
    const float* srcs[4] = { gW + cid * (CC*DHH), gM + cid * (CC*CC),
                             gq + ((size_t)bh * TT + c * CC) * DHH,
                             gk + ((size_t)bh * TT + c * CC) * DHH };
    const uint32_t stb = sb + (st * SEQ_STAGE) * 4;
    #pragma unroll
    for (int i = 0; i < 16; i++){
      int id = tid + i * 256;
      int mat = id >> 10, rem = id & 1023;
      int row = rem >> 4, c4 = rem & 15;
      cpasync16(stb + (mat * 4352 + row * 68 + c4 * 4) * 4,
                srcs[mat] + (size_t)row * 64 + c4 * 4);
    }
    {
      int row = tid >> 2, c4 = tid & 3;
      cpasync16(stb + (SEQ_U0 + row * 16 + c4 * 4) * 4,
                gU0 + cid * (CC*DHH) + (size_t)row * 64 + colb + c4 * 4);
    }
  };

  for (int i = tid; i < 64 * SP; i += 256){ sS[i] = 0.f; }
  load_chunk(0, 0); cpasync_commit();
  __syncthreads();

  for (int c = 0; c < NC; c++){
    const int st = c & 1;
    if (c + 1 < NC){ load_chunk(st ^ 1, c + 1); cpasync_commit();
                     asm volatile("cp.async.wait_group 1;" ::: "memory"); }
    else           { asm volatile("cp.async.wait_group 0;" ::: "memory"); }
    __syncthreads();

    const float* cW  = sm + st * SEQ_STAGE + SEQ_W;
    const float* cM  = sm + st * SEQ_STAGE + SEQ_M;
    const float* cQ  = sm + st * SEQ_STAGE + SEQ_Q;
    const float* cK  = sm + st * SEQ_STAGE + SEQ_K;
    const float* cU0 = sm + st * SEQ_STAGE + SEQ_U0;
    float* Op = go + ((size_t)bh * TT + c * CC) * DHH + colb;

    {
      float4 u0 = *(const float4*)&cU0[trow*16 + vo];
      unsigned long long a0, a1;
      { unsigned lo0=__float_as_uint(u0.x), hi0=__float_as_uint(u0.y);
        unsigned lo1=__float_as_uint(u0.z), hi1=__float_as_uint(u0.w);
        asm("mov.b64 %0, {%1, %2};" : "=l"(a0) : "r"(lo0), "r"(hi0));
        asm("mov.b64 %0, {%1, %2};" : "=l"(a1) : "r"(lo1), "r"(hi1)); }
      #pragma unroll 8
      for (int kk = 0; kk < 64; kk++){
        unsigned long long nw = dup2(-cW[trow*68 + kk]);
        ulonglong2 s2 = *(const ulonglong2*)&sS[kk*SP + vo];
        ffma2(a0, nw, s2.x);  ffma2(a1, nw, s2.y);
      }
      *(ulonglong2*)&sU[trow*SP + vo] = make_ulonglong2(a0, a1);
    }
    __syncthreads();

    {
      unsigned long long a0 = 0ull, a1 = 0ull;
      #pragma unroll 8
      for (int j = 0; j < 64; j++){
        unsigned long long qd = dup2(cQ[trow*68 + j]);
        ulonglong2 s2 = *(const ulonglong2*)&sS[j*SP + vo];
        ffma2(a0, qd, s2.x);  ffma2(a1, qd, s2.y);
      }
      #pragma unroll 8
      for (int s = 0; s < 64; s++){
        unsigned long long md = dup2(cM[trow*68 + s]);
        ulonglong2 u2 = *(const ulonglong2*)&sU[s*SP + vo];
        ffma2(a0, md, u2.x);  ffma2(a1, md, u2.y);
      }
      float2 o01 = unpk2(a0), o23 = unpk2(a1);
      *(float4*)&Op[trow*64 + vo] = make_float4(o01.x, o01.y, o23.x, o23.y);
    }
    __syncthreads();

    {
      ulonglong2 sacc = *(const ulonglong2*)&sS[trow*SP + vo];
      unsigned long long a0 = sacc.x, a1 = sacc.y;
      #pragma unroll 8
      for (int t = 0; t < 64; t++){
        unsigned long long kd = dup2(cK[t*68 + trow]);
        ulonglong2 u2 = *(const ulonglong2*)&sU[t*SP + vo];
        ffma2(a0, kd, u2.x);  ffma2(a1, kd, u2.y);
      }
      *(ulonglong2*)&sS[trow*SP + vo] = make_ulonglong2(a0, a1);
    }
    __syncthreads();
  }
}

// ---------------------------------------------------------------------------
// Per-head RMSNorm * rms_g -> [M,D] fp16
// ---------------------------------------------------------------------------
__global__ void rmsnorm_kernel(const float* __restrict__ O, const float* __restrict__ g,
                               __half* __restrict__ YH)
{
  const int m = blockIdx.x;
  const int b = m >> 11, t = m & (TT-1);
  const int tid = threadIdx.x;
  const int h = tid >> 4;
  const int dh0 = (tid & 15) * 4;

  float4 ov = *(const float4*)&O[(((size_t)(b * HH + h)) * TT + t) * DHH + dh0];
  float ss = ov.x*ov.x + ov.y*ov.y + ov.z*ov.z + ov.w*ov.w;
  #pragma unroll
  for (int off = 8; off > 0; off >>= 1)
    ss += __shfl_xor_sync(0xffffffffu, ss, off, 16);
  float sc = rsqrtf(ss * (1.f / 64.f) + 1e-6f);
  float4 gv = *(const float4*)&g[dh0];
  size_t base = (size_t)m * DD + tid * 4;
  *(__half2*)(YH + base)     = __floats2half2_rn(ov.x * sc * gv.x, ov.y * sc * gv.y);
  *(__half2*)(YH + base + 2) = __floats2half2_rn(ov.z * sc * gv.z, ov.w * sc * gv.w);
}

// ---------------------------------------------------------------------------
// Launch
// ---------------------------------------------------------------------------
extern "C" void kernel_launch(void* const* d_in, const int* in_sizes, int n_in,
                              void* d_out, int out_size)
{
  (void)in_sizes; (void)n_in; (void)out_size;
  const float* x  = (const float*)d_in[0];
  const float* Wq = (const float*)d_in[1];
  const float* Wk = (const float*)d_in[2];
  const float* Wv = (const float*)d_in[3];
  const float* Wb = (const float*)d_in[4];
  const float* cq = (const float*)d_in[5];
  const float* ck = (const float*)d_in[6];
  const float* cv = (const float*)d_in[7];
  const float* rg = (const float*)d_in[8];
  const float* Wo = (const float*)d_in[9];
  float* out = (float*)d_out;

  float *q, *k, *v, *beta, *o, *gW, *gU0, *gM, *wbt;
  __half *qch, *kch, *vch, *xh, *oh, *wt;
  cudaGetSymbolAddress((void**)&qch, g_qch);
  cudaGetSymbolAddress((void**)&kch, g_kch);
  cudaGetSymbolAddress((void**)&vch, g_vch);
  cudaGetSymbolAddress((void**)&q,   g_q);
  cudaGetSymbolAddress((void**)&k,   g_k);
  cudaGetSymbolAddress((void**)&v,   g_v);
  cudaGetSymbolAddress((void**)&beta, g_beta);
  cudaGetSymbolAddress((void**)&o,   g_o);
  cudaGetSymbolAddress((void**)&gW,  g_W);
  cudaGetSymbolAddress((void**)&gU0, g_U0);
  cudaGetSymbolAddress((void**)&gM,  g_M);
  cudaGetSymbolAddress((void**)&xh,  g_xh);
  cudaGetSymbolAddress((void**)&oh,  g_oh);
  cudaGetSymbolAddress((void**)&wt,  g_wt);
  cudaGetSymbolAddress((void**)&wbt, g_wbt);

  cudaFuncSetAttribute(gemm_mma<__half>, cudaFuncAttributeMaxDynamicSharedMemorySize, GEMM_SMEM);
  cudaFuncSetAttribute(gemm_mma<float>,  cudaFuncAttributeMaxDynamicSharedMemorySize, GEMM_SMEM);
  cudaFuncSetAttribute(wy_pre, cudaFuncAttributeMaxDynamicSharedMemorySize, PRE_TOT * 4);
  cudaFuncSetAttribute(wy_seq, cudaFuncAttributeMaxDynamicSharedMemorySize, SEQ_TOT * 4);

  const size_t WSZ = (size_t)DD * DD;

  tohalf_kernel<<<MM * DD / 1024, 256>>>(x, xh);
  wt4_kernel<<<dim3(32, 32, 4), dim3(32, 8)>>>(Wq, Wk, Wv, Wo, wt);
  wbt_kernel<<<64, 256>>>(Wb, wbt);

  gemm_mma<__half><<<dim3(24, MM/128), 256, GEMM_SMEM>>>(xh, wt, qch, kch, vch);

  beta_kernel<<<MM/8, 256>>>(x, wbt, beta);
  conv3_kernel<<<dim3(MM, 3), 256>>>(qch, kch, vch, cq, ck, cv, q, k, v);

  wy_pre<<<dim3(NC, NBH), 256, PRE_TOT * 4>>>(q, k, v, beta, gW, gU0, gM);
  wy_seq<<<dim3(4, NBH), 256, SEQ_TOT * 4>>>(q, k, gW, gU0, gM, o);

  rmsnorm_kernel<<<MM, 256>>>(o, rg, oh);
  gemm_mma<float><<<dim3(8, MM/128), 256, GEMM_SMEM>>>(oh, wt + 3*WSZ, out, out, out);
}